// round 1
// baseline (speedup 1.0000x reference)
#include <cuda_runtime.h>
#include <math.h>

#define B_    32
#define C_    384
#define Hh    32
#define Ww    32
#define N_    1024
#define S_    4
#define NE    256
#define NHEAD 6
#define HD    64
#define EPS_  1e-5f

// ---------------- scratch (device globals; no allocation) ----------------
__device__ float g_Q [B_*C_*N_];
__device__ float g_K [B_*C_*N_];
__device__ float g_V [B_*C_*N_];   // raw v
__device__ float g_V2[B_*C_*N_];   // v + pe
__device__ float g_AO[B_*N_*C_];   // attention output, laid out [B][N][C] (z layout)
__device__ float g_P [B_*C_*N_];   // proj output
__device__ float g_mean[C_];
__device__ float g_rstd[C_];

// ---------------- K1: fused QKV GEMM ----------------
// out[b,o,n] = sum_c W[o,c] * x[b,c,n], rows 0..383 -> Q, 384..767 -> K, 768..1151 -> V
// grid: (N_/64, 1152/64, B_), block 256, tile 64x64xK16, micro 4x4
__global__ __launch_bounds__(256) void qkv_gemm(
    const float* __restrict__ x,
    const float* __restrict__ Wq,
    const float* __restrict__ Wk,
    const float* __restrict__ Wv)
{
    __shared__ float As[16][64];
    __shared__ float Bs[16][64];

    const int b  = blockIdx.z;
    const int ow = blockIdx.y * 64;     // 0..1151
    const int n0 = blockIdx.x * 64;

    const float* W;
    float* outbuf;
    int orow;
    if (ow < 384)       { W = Wq; outbuf = g_Q; orow = ow; }
    else if (ow < 768)  { W = Wk; outbuf = g_K; orow = ow - 384; }
    else                { W = Wv; outbuf = g_V; orow = ow - 768; }

    const float* X = x + (size_t)b * C_ * N_;
    float* O = outbuf + (size_t)b * C_ * N_ + (size_t)orow * N_ + n0;

    const int t  = threadIdx.x;
    const int tx = t & 15;        // n dir
    const int ty = t >> 4;        // m dir

    // loader indices
    const int aRow  = t >> 2;          // 0..63 (o)
    const int aCol4 = (t & 3) * 4;     // c offset within BK
    const int bRow  = t >> 4;          // 0..15 (k)
    const int bCol4 = (t & 15) * 4;    // n offset

    float acc[4][4] = {};

    for (int k0 = 0; k0 < C_; k0 += 16) {
        float4 av = *(const float4*)(W + (size_t)(orow + aRow) * C_ + k0 + aCol4);
        As[aCol4 + 0][aRow] = av.x;
        As[aCol4 + 1][aRow] = av.y;
        As[aCol4 + 2][aRow] = av.z;
        As[aCol4 + 3][aRow] = av.w;
        *(float4*)&Bs[bRow][bCol4] =
            *(const float4*)(X + (size_t)(k0 + bRow) * N_ + n0 + bCol4);
        __syncthreads();
#pragma unroll
        for (int k = 0; k < 16; k++) {
            float4 a  = *(const float4*)&As[k][ty * 4];
            float4 bb = *(const float4*)&Bs[k][tx * 4];
            acc[0][0] += a.x * bb.x; acc[0][1] += a.x * bb.y; acc[0][2] += a.x * bb.z; acc[0][3] += a.x * bb.w;
            acc[1][0] += a.y * bb.x; acc[1][1] += a.y * bb.y; acc[1][2] += a.y * bb.z; acc[1][3] += a.y * bb.w;
            acc[2][0] += a.z * bb.x; acc[2][1] += a.z * bb.y; acc[2][2] += a.z * bb.z; acc[2][3] += a.z * bb.w;
            acc[3][0] += a.w * bb.x; acc[3][1] += a.w * bb.y; acc[3][2] += a.w * bb.z; acc[3][3] += a.w * bb.w;
        }
        __syncthreads();
    }
#pragma unroll
    for (int i = 0; i < 4; i++) {
        float4 r = make_float4(acc[i][0], acc[i][1], acc[i][2], acc[i][3]);
        *(float4*)(O + (size_t)(ty * 4 + i) * N_ + tx * 4) = r;
    }
}

// ---------------- K2: depthwise 3x3 PE + add ----------------
__global__ __launch_bounds__(256) void dwconv_kernel(const float* __restrict__ Wpe)
{
    int idx = blockIdx.x * 256 + threadIdx.x;   // over B*C*N
    int n = idx & (N_ - 1);
    int c = (idx / N_) % C_;
    int b = idx / (N_ * C_);
    int h = n >> 5, w = n & 31;

    const float* vb = g_V + ((size_t)b * C_ + c) * N_;
    const float* wp = Wpe + c * 9;

    float s = 0.f;
#pragma unroll
    for (int kh = -1; kh <= 1; kh++) {
        int hh = h + kh;
        if (hh < 0 || hh >= Hh) continue;
#pragma unroll
        for (int kw = -1; kw <= 1; kw++) {
            int ww = w + kw;
            if (ww < 0 || ww >= Ww) continue;
            s += wp[(kh + 1) * 3 + (kw + 1)] * vb[hh * Ww + ww];
        }
    }
    g_V2[idx] = vb[n] + s;
}

// ---------------- K3: attention ----------------
// One CTA per (be, head, 64-row n-tile). 512 threads.
// smem (floats):
//   Qs  @ 0      : [64][64]       (4096)
//   Ks  @ 4096   : [64][256]      (16384)   -> region0 ends at 20480
//   Pt  @ 0      : [256][68]      (17408)   reuses Qs+Ks after scores
//   Sc  @ 20480  : [64][260]      (16640)
//   Vs  @ 37120  : [256][66]      (16896)
//   total 54016 floats = 216064 bytes
#define ATTN_SMEM_FLOATS 54016
#define PT_STRIDE 68
#define SC_STRIDE 260
#define VS_STRIDE 66

__global__ __launch_bounds__(512, 1) void attn_kernel()
{
    extern __shared__ float sm[];
    float* Qs = sm;                 // [64][64]
    float* Ks = sm + 4096;          // [64][256]
    float* Pt = sm;                 // [256][PT_STRIDE]
    float* Sc = sm + 20480;         // [64][SC_STRIDE]
    float* Vs = sm + 37120;         // [256][VS_STRIDE]

    const int nt = blockIdx.x;      // 0..3 (n-tile of 64)
    const int h  = blockIdx.y;      // 0..5
    const int be = blockIdx.z;      // 0..127
    const int b  = be >> 2;
    const int sP = be & 3;
    const int n0 = nt * 64;

    const int t = threadIdx.x;

    const float* Qg = g_Q  + ((size_t)b * C_ + h * HD) * N_ + sP * NE;
    const float* Kg = g_K  + ((size_t)b * C_ + h * HD) * N_ + sP * NE;
    const float* Vg = g_V2 + ((size_t)b * C_ + h * HD) * N_ + sP * NE;

    // load Qs[d][n] (64x64)
    for (int i = t; i < 64 * 16; i += 512) {
        int d = i >> 4, n4 = (i & 15) * 4;
        *(float4*)&Qs[d * 64 + n4] = *(const float4*)(Qg + (size_t)d * N_ + n0 + n4);
    }
    // load Ks[d][m] (64x256)
    for (int i = t; i < 64 * 64; i += 512) {
        int d = i >> 6, m4 = (i & 63) * 4;
        *(float4*)&Ks[d * 256 + m4] = *(const float4*)(Kg + (size_t)d * N_ + m4);
    }
    // load Vs[m][d] (transposed store, stride 66)
    for (int i = t; i < 64 * 64; i += 512) {
        int d = i >> 6, m4 = (i & 63) * 4;
        float4 v = *(const float4*)(Vg + (size_t)d * N_ + m4);
        Vs[(m4 + 0) * VS_STRIDE + d] = v.x;
        Vs[(m4 + 1) * VS_STRIDE + d] = v.y;
        Vs[(m4 + 2) * VS_STRIDE + d] = v.z;
        Vs[(m4 + 3) * VS_STRIDE + d] = v.w;
    }
    __syncthreads();

    // ---- scores: S[n][m] = sum_d Qs[d][n]*Ks[d][m] ----
    {
        const int tx = t & 63;      // m dir: m = tx*4
        const int ty = t >> 6;      // 0..7
        float acc[2][4][4] = {};
        for (int k = 0; k < 64; k++) {
            float4 b4 = *(const float4*)&Ks[k * 256 + tx * 4];
#pragma unroll
            for (int nh = 0; nh < 2; nh++) {
                float4 a = *(const float4*)&Qs[k * 64 + (nh * 8 + ty) * 4];
                float* A = (float*)&a;
#pragma unroll
                for (int i = 0; i < 4; i++) {
                    acc[nh][i][0] += A[i] * b4.x;
                    acc[nh][i][1] += A[i] * b4.y;
                    acc[nh][i][2] += A[i] * b4.z;
                    acc[nh][i][3] += A[i] * b4.w;
                }
            }
        }
#pragma unroll
        for (int nh = 0; nh < 2; nh++)
#pragma unroll
            for (int i = 0; i < 4; i++) {
                int n = (nh * 8 + ty) * 4 + i;
                *(float4*)&Sc[n * SC_STRIDE + tx * 4] =
                    make_float4(acc[nh][i][0], acc[nh][i][1], acc[nh][i][2], acc[nh][i][3]);
            }
    }
    __syncthreads();

    // ---- softmax per row (warp per row); write normalized into Pt[m][n] ----
    {
        const int warp = t >> 5, lane = t & 31;
        const float scale = 0.125f;   // hd^-0.5 = 1/8
        for (int r = warp; r < 64; r += 16) {
            const float* row = &Sc[r * SC_STRIDE];
            float vals[8];
            float mx = -1e30f;
#pragma unroll
            for (int j = 0; j < 8; j++) {
                vals[j] = row[lane + 32 * j] * scale;
                mx = fmaxf(mx, vals[j]);
            }
#pragma unroll
            for (int o = 16; o > 0; o >>= 1)
                mx = fmaxf(mx, __shfl_xor_sync(0xffffffffu, mx, o));
            float sum = 0.f;
#pragma unroll
            for (int j = 0; j < 8; j++) {
                vals[j] = __expf(vals[j] - mx);
                sum += vals[j];
            }
#pragma unroll
            for (int o = 16; o > 0; o >>= 1)
                sum += __shfl_xor_sync(0xffffffffu, sum, o);
            float inv = 1.f / sum;
#pragma unroll
            for (int j = 0; j < 8; j++)
                Pt[(lane + 32 * j) * PT_STRIDE + r] = vals[j] * inv;
        }
    }
    __syncthreads();

    // ---- AV: av[n][d] = sum_m Pt[m][n] * Vs[m][d] ----
    {
        const int tx = t & 31;      // d dir: d = tx*2
        const int ty = t >> 5;      // 0..15, n = ty*4
        float o[4][2] = {};
        for (int k = 0; k < 256; k++) {
            float4 a  = *(const float4*)&Pt[k * PT_STRIDE + ty * 4];
            float2 b2 = *(const float2*)&Vs[k * VS_STRIDE + tx * 2];
            float* A = (float*)&a;
#pragma unroll
            for (int i = 0; i < 4; i++) {
                o[i][0] += A[i] * b2.x;
                o[i][1] += A[i] * b2.y;
            }
        }
        // scatter into torch-faithful layout: AO[b][nf][cz]
#pragma unroll
        for (int i = 0; i < 4; i++) {
#pragma unroll
            for (int j = 0; j < 2; j++) {
                int n   = n0 + ty * 4 + i;          // 0..255 within area
                int d   = tx * 2 + j;               // 0..63
                int lin = (h * HD + d) * NE + n;    // 0..98303
                int ne2 = lin / C_;
                int cz  = lin - ne2 * C_;
                int nf  = ne2 * S_ + sP;
                g_AO[((size_t)b * N_ + nf) * C_ + cz] = o[i][j];
            }
        }
    }
}

// ---------------- K4: proj GEMM ----------------
// P[b,o,nf] = sum_c Wproj[o,c] * AO[b][nf][c]
// grid: (N_/64, C_/64, B_), block 256
__global__ __launch_bounds__(256) void proj_gemm(const float* __restrict__ Wp)
{
    __shared__ float As[16][64];
    __shared__ float Bs[16][64];

    const int b  = blockIdx.z;
    const int o0 = blockIdx.y * 64;
    const int n0 = blockIdx.x * 64;

    const int t  = threadIdx.x;
    const int tx = t & 15;
    const int ty = t >> 4;

    const int aRow  = t >> 2;
    const int aCol4 = (t & 3) * 4;
    const int bN    = t & 63;          // 0..63 (nf)
    const int bK4   = (t >> 6) * 4;    // 0,4,8,12

    const float* AOb = g_AO + (size_t)b * N_ * C_;
    float* O = g_P + (size_t)b * C_ * N_ + (size_t)o0 * N_ + n0;

    float acc[4][4] = {};

    for (int k0 = 0; k0 < C_; k0 += 16) {
        float4 av = *(const float4*)(Wp + (size_t)(o0 + aRow) * C_ + k0 + aCol4);
        As[aCol4 + 0][aRow] = av.x;
        As[aCol4 + 1][aRow] = av.y;
        As[aCol4 + 2][aRow] = av.z;
        As[aCol4 + 3][aRow] = av.w;
        float4 bv = *(const float4*)(AOb + (size_t)(n0 + bN) * C_ + k0 + bK4);
        Bs[bK4 + 0][bN] = bv.x;
        Bs[bK4 + 1][bN] = bv.y;
        Bs[bK4 + 2][bN] = bv.z;
        Bs[bK4 + 3][bN] = bv.w;
        __syncthreads();
#pragma unroll
        for (int k = 0; k < 16; k++) {
            float4 a  = *(const float4*)&As[k][ty * 4];
            float4 bb = *(const float4*)&Bs[k][tx * 4];
            acc[0][0] += a.x * bb.x; acc[0][1] += a.x * bb.y; acc[0][2] += a.x * bb.z; acc[0][3] += a.x * bb.w;
            acc[1][0] += a.y * bb.x; acc[1][1] += a.y * bb.y; acc[1][2] += a.y * bb.z; acc[1][3] += a.y * bb.w;
            acc[2][0] += a.z * bb.x; acc[2][1] += a.z * bb.y; acc[2][2] += a.z * bb.z; acc[2][3] += a.z * bb.w;
            acc[3][0] += a.w * bb.x; acc[3][1] += a.w * bb.y; acc[3][2] += a.w * bb.z; acc[3][3] += a.w * bb.w;
        }
        __syncthreads();
    }
#pragma unroll
    for (int i = 0; i < 4; i++) {
        float4 r = make_float4(acc[i][0], acc[i][1], acc[i][2], acc[i][3]);
        *(float4*)(O + (size_t)(ty * 4 + i) * N_ + tx * 4) = r;
    }
}

// ---------------- K5: BN stats (deterministic) ----------------
__global__ __launch_bounds__(256) void bn_stats()
{
    const int o = blockIdx.x;
    const int t = threadIdx.x;
    float s = 0.f, sq = 0.f;
    for (int i = t; i < B_ * N_; i += 256) {
        int b = i >> 10, n = i & (N_ - 1);
        float v = g_P[((size_t)b * C_ + o) * N_ + n];
        s  += v;
        sq += v * v;
    }
    __shared__ float rs[256], rq[256];
    rs[t] = s; rq[t] = sq;
    __syncthreads();
    for (int st = 128; st > 0; st >>= 1) {
        if (t < st) { rs[t] += rs[t + st]; rq[t] += rq[t + st]; }
        __syncthreads();
    }
    if (t == 0) {
        float inv_n = 1.f / (float)(B_ * N_);
        float mu  = rs[0] * inv_n;
        float var = rq[0] * inv_n - mu * mu;
        g_mean[o] = mu;
        g_rstd[o] = rsqrtf(var + EPS_);
    }
}

// ---------------- K6: residual + BN normalize ----------------
__global__ __launch_bounds__(256) void final_kernel(
    const float* __restrict__ x,
    const float* __restrict__ gamma,
    const float* __restrict__ beta,
    float* __restrict__ out)
{
    int idx = blockIdx.x * 256 + threadIdx.x;
    int c = (idx / N_) % C_;
    float v = g_P[idx];
    out[idx] = x[idx] + gamma[c] * (v - g_mean[c]) * g_rstd[c] + beta[c];
}

// ---------------- launch ----------------
extern "C" void kernel_launch(void* const* d_in, const int* in_sizes, int n_in,
                              void* d_out, int out_size)
{
    const float* x     = (const float*)d_in[0];
    const float* Wq    = (const float*)d_in[1];
    const float* Wk    = (const float*)d_in[2];
    const float* Wv    = (const float*)d_in[3];
    const float* Wpe   = (const float*)d_in[4];
    const float* Wproj = (const float*)d_in[5];
    const float* gamma = (const float*)d_in[6];
    const float* beta  = (const float*)d_in[7];
    float* out = (float*)d_out;

    static bool attr_set = false;
    if (!attr_set) {
        cudaFuncSetAttribute(attn_kernel,
                             cudaFuncAttributeMaxDynamicSharedMemorySize,
                             ATTN_SMEM_FLOATS * (int)sizeof(float));
        attr_set = true;
    }

    dim3 g1(N_ / 64, 1152 / 64, B_);
    qkv_gemm<<<g1, 256>>>(x, Wq, Wk, Wv);

    dwconv_kernel<<<(B_ * C_ * N_) / 256, 256>>>(Wpe);

    dim3 g3(4, NHEAD, 128);
    attn_kernel<<<g3, 512, ATTN_SMEM_FLOATS * sizeof(float)>>>();

    dim3 g4(N_ / 64, C_ / 64, B_);
    proj_gemm<<<g4, 256>>>(Wproj);

    bn_stats<<<C_, 256>>>();

    final_kernel<<<(B_ * C_ * N_) / 256, 256>>>(x, gamma, beta, out);
}

// round 3
// speedup vs baseline: 1.8651x; 1.8651x over previous
#include <cuda_runtime.h>
#include <math.h>
#include <stdint.h>

#define B_    32
#define C_    384
#define Hh    32
#define Ww    32
#define N_    1024
#define S_    4
#define NE    256
#define NHEAD 6
#define HD    64
#define EPS_  1e-5f

// ---------------- scratch (device globals; no allocation) ----------------
__device__ float g_Q [B_*C_*N_];   // [b][c][n]
__device__ float g_K [B_*C_*N_];
__device__ float g_V [B_*C_*N_];
__device__ float g_V2[B_*C_*N_];
__device__ float g_AO[B_*C_*N_];   // attention output [b][cz][nf]  (same layout as x)
__device__ float g_P [B_*C_*N_];   // proj output [b][c][n]
__device__ float g_mean[C_];
__device__ float g_rstd[C_];

// ---------------- generic-PTX helpers ----------------
__device__ __forceinline__ uint32_t smem_u32(const void* p) {
    uint32_t a;
    asm("{ .reg .u64 t; cvta.to.shared.u64 t, %1; cvt.u32.u64 %0, t; }" : "=r"(a) : "l"(p));
    return a;
}
__device__ __forceinline__ void cp16(uint32_t dst, const void* src) {
    asm volatile("cp.async.cg.shared.global [%0], [%1], 16;" :: "r"(dst), "l"(src) : "memory");
}
#define CP_COMMIT() asm volatile("cp.async.commit_group;" ::: "memory")
#define CP_WAIT(n)  asm volatile("cp.async.wait_group %0;" :: "n"(n) : "memory")

__device__ __forceinline__ uint32_t f2tf32(float f) {
    uint32_t u;
    asm("cvt.rna.tf32.f32 %0, %1;" : "=r"(u) : "f"(f));
    return u;
}
__device__ __forceinline__ void mma_tf32(float c[4],
    uint32_t a0, uint32_t a1, uint32_t a2, uint32_t a3, uint32_t b0, uint32_t b1)
{
    asm volatile("mma.sync.aligned.m16n8k8.row.col.f32.tf32.tf32.f32 "
        "{%0,%1,%2,%3}, {%4,%5,%6,%7}, {%8,%9}, {%0,%1,%2,%3};"
        : "+f"(c[0]), "+f"(c[1]), "+f"(c[2]), "+f"(c[3])
        : "r"(a0), "r"(a1), "r"(a2), "r"(a3), "r"(b0), "r"(b1));
}

// ---------------- tf32 mma.sync GEMM ----------------
// D[b][o][n] = sum_c A[o][c] * Bsrc[b][c][n]
// CTA tile 128(o) x 128(n), K chunks of 32, double-buffered cp.async.
// 8 warps: warp_m = wid&1 (2 of 64), warp_n = wid>>1 (4 of 32).
// smem: As[2][128][36] fp32, Bs[2][32][136] fp32
#define A_STR 36
#define B_STR 136
#define A_CH  (128 * A_STR)          // 4608 floats / buffer
#define B_CH  (32 * B_STR)           // 4352 floats / buffer
#define A_TOT (2 * A_CH)             // 9216
#define GS_FLOATS (A_TOT + 2 * B_CH) // 17920 floats = 71680 B

__global__ __launch_bounds__(256) void gemm_mma(
    const float* __restrict__ W0,
    const float* __restrict__ W1,
    const float* __restrict__ W2,
    const float* __restrict__ Bsrc0,
    int mode)   // 0: QKV (y = fam*3+ot), 1: proj (y = ot)
{
    extern __shared__ float sm[];
    float* As = sm;
    float* Bs = sm + A_TOT;
    const uint32_t sb = smem_u32(sm);

    const int t   = threadIdx.x;
    const int wid = t >> 5;
    const int lane = t & 31;
    const int g  = lane >> 2;     // group id 0..7
    const int tg = lane & 3;      // thread in group 0..3
    const int wm = wid & 1;       // 0..1
    const int wn = wid >> 1;      // 0..3

    const int n0 = blockIdx.x * 128;
    const int y  = blockIdx.y;
    const int b  = blockIdx.z;

    const float* W;
    float* outbuf;
    int o0;
    if (mode == 0) {
        int fam = y / 3;
        o0 = (y % 3) * 128;
        W = (fam == 0) ? W0 : (fam == 1) ? W1 : W2;
        outbuf = (fam == 0) ? g_Q : (fam == 1) ? g_K : g_V;
    } else {
        o0 = y * 128;
        W = W0;
        outbuf = g_P;
    }
    const float* Bp = ((mode == 0) ? Bsrc0 : g_AO) + (size_t)b * C_ * N_;

    // accumulators: [mt][nt][4]
    float acc[4][4][4];
#pragma unroll
    for (int i = 0; i < 4; i++)
#pragma unroll
        for (int j = 0; j < 4; j++) {
            acc[i][j][0] = 0.f; acc[i][j][1] = 0.f;
            acc[i][j][2] = 0.f; acc[i][j][3] = 0.f;
        }

    // ---- async loaders ----
    // A chunk: 128 rows x 32 floats (8 float4/row), 1024 xfers
    // B chunk: 32 rows x 128 floats (32 float4/row), 1024 xfers
    auto issue = [&](int kc, int buf) {
        const int k0 = kc * 32;
        uint32_t adst = sb + (uint32_t)(buf * A_CH) * 4u;
        uint32_t bdst = sb + (uint32_t)(A_TOT + buf * B_CH) * 4u;
#pragma unroll
        for (int r = 0; r < 4; r++) {
            int i = t + r * 256;
            int row = i >> 3, c4 = (i & 7) * 4;
            cp16(adst + (uint32_t)(row * A_STR + c4) * 4u,
                 W + (size_t)(o0 + row) * C_ + k0 + c4);
        }
#pragma unroll
        for (int r = 0; r < 4; r++) {
            int i = t + r * 256;
            int row = i >> 5, c4 = (i & 31) * 4;
            cp16(bdst + (uint32_t)(row * B_STR + c4) * 4u,
                 Bp + (size_t)(k0 + row) * N_ + n0 + c4);
        }
    };

    issue(0, 0);
    CP_COMMIT();

    for (int kc = 0; kc < 12; kc++) {
        const int buf = kc & 1;
        if (kc + 1 < 12) {
            issue(kc + 1, buf ^ 1);
            CP_COMMIT();
            CP_WAIT(1);
        } else {
            CP_WAIT(0);
        }
        __syncthreads();

        const float* As_ = As + buf * A_CH;
        const float* Bs_ = Bs + buf * B_CH;

#pragma unroll
        for (int ks = 0; ks < 4; ks++) {
            const int k0 = ks * 8;
            uint32_t af[4][4], bf[4][2];
#pragma unroll
            for (int mt = 0; mt < 4; mt++) {
                const float* ap = As_ + (wm * 64 + mt * 16 + g) * A_STR + k0 + tg;
                af[mt][0] = f2tf32(ap[0]);
                af[mt][1] = f2tf32(ap[8 * A_STR]);
                af[mt][2] = f2tf32(ap[4]);
                af[mt][3] = f2tf32(ap[8 * A_STR + 4]);
            }
#pragma unroll
            for (int nt = 0; nt < 4; nt++) {
                const float* bp = Bs_ + (k0 + tg) * B_STR + wn * 32 + nt * 8 + g;
                bf[nt][0] = f2tf32(bp[0]);
                bf[nt][1] = f2tf32(bp[4 * B_STR]);
            }
#pragma unroll
            for (int mt = 0; mt < 4; mt++)
#pragma unroll
                for (int nt = 0; nt < 4; nt++)
                    mma_tf32(acc[mt][nt], af[mt][0], af[mt][1], af[mt][2], af[mt][3],
                             bf[nt][0], bf[nt][1]);
        }
        __syncthreads();
    }

    // ---- epilogue ----
    float* D = outbuf + (size_t)b * C_ * N_;
#pragma unroll
    for (int mt = 0; mt < 4; mt++) {
        const int o = o0 + wm * 64 + mt * 16 + g;
#pragma unroll
        for (int nt = 0; nt < 4; nt++) {
            const int n = n0 + wn * 32 + nt * 8 + tg * 2;
            *(float2*)(D + (size_t)o * N_ + n)       = make_float2(acc[mt][nt][0], acc[mt][nt][1]);
            *(float2*)(D + (size_t)(o + 8) * N_ + n) = make_float2(acc[mt][nt][2], acc[mt][nt][3]);
        }
    }
}

// ---------------- K2: depthwise 3x3 PE + add ----------------
__global__ __launch_bounds__(256) void dwconv_kernel(const float* __restrict__ Wpe)
{
    int idx = blockIdx.x * 256 + threadIdx.x;
    int n = idx & (N_ - 1);
    int c = (idx / N_) % C_;
    int b = idx / (N_ * C_);
    int h = n >> 5, w = n & 31;

    const float* vb = g_V + ((size_t)b * C_ + c) * N_;
    const float* wp = Wpe + c * 9;

    float s = 0.f;
#pragma unroll
    for (int kh = -1; kh <= 1; kh++) {
        int hh = h + kh;
        if (hh < 0 || hh >= Hh) continue;
#pragma unroll
        for (int kw = -1; kw <= 1; kw++) {
            int ww = w + kw;
            if (ww < 0 || ww >= Ww) continue;
            s += wp[(kh + 1) * 3 + (kw + 1)] * vb[hh * Ww + ww];
        }
    }
    g_V2[idx] = vb[n] + s;
}

// ---------------- K3: attention (SIMT, writes AO in [b][cz][nf]) ----------------
#define ATTN_SMEM_FLOATS 54016
#define PT_STRIDE 68
#define SC_STRIDE 260
#define VS_STRIDE 66

__global__ __launch_bounds__(512, 1) void attn_kernel()
{
    extern __shared__ float sm[];
    float* Qs = sm;                 // [64][64]
    float* Ks = sm + 4096;          // [64][256]
    float* Pt = sm;                 // [256][PT_STRIDE]  (reuses Qs+Ks)
    float* Sc = sm + 20480;         // [64][SC_STRIDE]
    float* Vs = sm + 37120;         // [256][VS_STRIDE]

    const int nt = blockIdx.x;
    const int h  = blockIdx.y;
    const int be = blockIdx.z;
    const int b  = be >> 2;
    const int sP = be & 3;
    const int n0 = nt * 64;

    const int t = threadIdx.x;

    const float* Qg = g_Q  + ((size_t)b * C_ + h * HD) * N_ + sP * NE;
    const float* Kg = g_K  + ((size_t)b * C_ + h * HD) * N_ + sP * NE;
    const float* Vg = g_V2 + ((size_t)b * C_ + h * HD) * N_ + sP * NE;

    for (int i = t; i < 64 * 16; i += 512) {
        int d = i >> 4, n4 = (i & 15) * 4;
        *(float4*)&Qs[d * 64 + n4] = *(const float4*)(Qg + (size_t)d * N_ + n0 + n4);
    }
    for (int i = t; i < 64 * 64; i += 512) {
        int d = i >> 6, m4 = (i & 63) * 4;
        *(float4*)&Ks[d * 256 + m4] = *(const float4*)(Kg + (size_t)d * N_ + m4);
    }
    for (int i = t; i < 64 * 64; i += 512) {
        int d = i >> 6, m4 = (i & 63) * 4;
        float4 v = *(const float4*)(Vg + (size_t)d * N_ + m4);
        Vs[(m4 + 0) * VS_STRIDE + d] = v.x;
        Vs[(m4 + 1) * VS_STRIDE + d] = v.y;
        Vs[(m4 + 2) * VS_STRIDE + d] = v.z;
        Vs[(m4 + 3) * VS_STRIDE + d] = v.w;
    }
    __syncthreads();

    {
        const int tx = t & 63;
        const int ty = t >> 6;
        float acc[2][4][4] = {};
        for (int k = 0; k < 64; k++) {
            float4 b4 = *(const float4*)&Ks[k * 256 + tx * 4];
#pragma unroll
            for (int nh = 0; nh < 2; nh++) {
                float4 a = *(const float4*)&Qs[k * 64 + (nh * 8 + ty) * 4];
                float* A = (float*)&a;
#pragma unroll
                for (int i = 0; i < 4; i++) {
                    acc[nh][i][0] += A[i] * b4.x;
                    acc[nh][i][1] += A[i] * b4.y;
                    acc[nh][i][2] += A[i] * b4.z;
                    acc[nh][i][3] += A[i] * b4.w;
                }
            }
        }
#pragma unroll
        for (int nh = 0; nh < 2; nh++)
#pragma unroll
            for (int i = 0; i < 4; i++) {
                int n = (nh * 8 + ty) * 4 + i;
                *(float4*)&Sc[n * SC_STRIDE + tx * 4] =
                    make_float4(acc[nh][i][0], acc[nh][i][1], acc[nh][i][2], acc[nh][i][3]);
            }
    }
    __syncthreads();

    {
        const int warp = t >> 5, lane = t & 31;
        const float scale = 0.125f;
        for (int r = warp; r < 64; r += 16) {
            const float* row = &Sc[r * SC_STRIDE];
            float vals[8];
            float mx = -1e30f;
#pragma unroll
            for (int j = 0; j < 8; j++) {
                vals[j] = row[lane + 32 * j] * scale;
                mx = fmaxf(mx, vals[j]);
            }
#pragma unroll
            for (int o = 16; o > 0; o >>= 1)
                mx = fmaxf(mx, __shfl_xor_sync(0xffffffffu, mx, o));
            float sum = 0.f;
#pragma unroll
            for (int j = 0; j < 8; j++) {
                vals[j] = __expf(vals[j] - mx);
                sum += vals[j];
            }
#pragma unroll
            for (int o = 16; o > 0; o >>= 1)
                sum += __shfl_xor_sync(0xffffffffu, sum, o);
            float inv = 1.f / sum;
#pragma unroll
            for (int j = 0; j < 8; j++)
                Pt[(lane + 32 * j) * PT_STRIDE + r] = vals[j] * inv;
        }
    }
    __syncthreads();

    {
        const int tx = t & 31;
        const int ty = t >> 5;
        float o[4][2] = {};
        for (int k = 0; k < 256; k++) {
            float4 a  = *(const float4*)&Pt[k * PT_STRIDE + ty * 4];
            float2 b2 = *(const float2*)&Vs[k * VS_STRIDE + tx * 2];
            float* A = (float*)&a;
#pragma unroll
            for (int i = 0; i < 4; i++) {
                o[i][0] += A[i] * b2.x;
                o[i][1] += A[i] * b2.y;
            }
        }
        // torch-faithful scrambled layout, stored c-major: AO[b][cz][nf]
#pragma unroll
        for (int i = 0; i < 4; i++) {
#pragma unroll
            for (int j = 0; j < 2; j++) {
                int n   = n0 + ty * 4 + i;
                int d   = tx * 2 + j;
                int lin = (h * HD + d) * NE + n;
                int ne2 = lin / C_;
                int cz  = lin - ne2 * C_;
                int nf  = ne2 * S_ + sP;
                g_AO[((size_t)b * C_ + cz) * N_ + nf] = o[i][j];
            }
        }
    }
}

// ---------------- K5: BN stats (deterministic) ----------------
__global__ __launch_bounds__(256) void bn_stats()
{
    const int o = blockIdx.x;
    const int t = threadIdx.x;
    float s = 0.f, sq = 0.f;
    for (int i = t; i < B_ * N_; i += 256) {
        int b = i >> 10, n = i & (N_ - 1);
        float v = g_P[((size_t)b * C_ + o) * N_ + n];
        s  += v;
        sq += v * v;
    }
    __shared__ float rs[256], rq[256];
    rs[t] = s; rq[t] = sq;
    __syncthreads();
    for (int st = 128; st > 0; st >>= 1) {
        if (t < st) { rs[t] += rs[t + st]; rq[t] += rq[t + st]; }
        __syncthreads();
    }
    if (t == 0) {
        float inv_n = 1.f / (float)(B_ * N_);
        float mu  = rs[0] * inv_n;
        float var = rq[0] * inv_n - mu * mu;
        g_mean[o] = mu;
        g_rstd[o] = rsqrtf(var + EPS_);
    }
}

// ---------------- K6: residual + BN normalize ----------------
__global__ __launch_bounds__(256) void final_kernel(
    const float* __restrict__ x,
    const float* __restrict__ gamma,
    const float* __restrict__ beta,
    float* __restrict__ out)
{
    int idx = blockIdx.x * 256 + threadIdx.x;
    int c = (idx / N_) % C_;
    float v = g_P[idx];
    out[idx] = x[idx] + gamma[c] * (v - g_mean[c]) * g_rstd[c] + beta[c];
}

// ---------------- launch ----------------
extern "C" void kernel_launch(void* const* d_in, const int* in_sizes, int n_in,
                              void* d_out, int out_size)
{
    const float* x     = (const float*)d_in[0];
    const float* Wq    = (const float*)d_in[1];
    const float* Wk    = (const float*)d_in[2];
    const float* Wv    = (const float*)d_in[3];
    const float* Wpe   = (const float*)d_in[4];
    const float* Wproj = (const float*)d_in[5];
    const float* gamma = (const float*)d_in[6];
    const float* beta  = (const float*)d_in[7];
    float* out = (float*)d_out;

    static bool attr_set = false;
    if (!attr_set) {
        cudaFuncSetAttribute(gemm_mma, cudaFuncAttributeMaxDynamicSharedMemorySize,
                             GS_FLOATS * (int)sizeof(float));
        cudaFuncSetAttribute(attn_kernel, cudaFuncAttributeMaxDynamicSharedMemorySize,
                             ATTN_SMEM_FLOATS * (int)sizeof(float));
        attr_set = true;
    }

    gemm_mma<<<dim3(N_ / 128, 9, B_), 256, GS_FLOATS * sizeof(float)>>>(Wq, Wk, Wv, x, 0);

    dwconv_kernel<<<(B_ * C_ * N_) / 256, 256>>>(Wpe);

    attn_kernel<<<dim3(4, NHEAD, 128), 512, ATTN_SMEM_FLOATS * sizeof(float)>>>();

    gemm_mma<<<dim3(N_ / 128, 3, B_), 256, GS_FLOATS * sizeof(float)>>>(Wproj, Wproj, Wproj, nullptr, 1);

    bn_stats<<<C_, 256>>>();

    final_kernel<<<(B_ * C_ * N_) / 256, 256>>>(x, gamma, beta, out);
}

// round 4
// speedup vs baseline: 2.7495x; 1.4742x over previous
#include <cuda_runtime.h>
#include <math.h>
#include <stdint.h>

#define B_    32
#define C_    384
#define Hh    32
#define Ww    32
#define N_    1024
#define S_    4
#define NE    256
#define NHEAD 6
#define HD    64
#define EPS_  1e-5f

// ---------------- scratch (device globals; no allocation) ----------------
__device__ float g_Q [B_*C_*N_];   // [b][c][n]
__device__ float g_K [B_*C_*N_];
__device__ float g_V [B_*C_*N_];
__device__ float g_V2[B_*C_*N_];
__device__ float g_AO[B_*C_*N_];   // attention output [b][cz][nf]
__device__ float g_P [B_*C_*N_];   // proj output [b][c][n]
__device__ float g_mean[C_];
__device__ float g_rstd[C_];

// ---------------- generic-PTX helpers ----------------
__device__ __forceinline__ uint32_t smem_u32(const void* p) {
    uint32_t a;
    asm("{ .reg .u64 t; cvta.to.shared.u64 t, %1; cvt.u32.u64 %0, t; }" : "=r"(a) : "l"(p));
    return a;
}
__device__ __forceinline__ void cp16(uint32_t dst, const void* src) {
    asm volatile("cp.async.cg.shared.global [%0], [%1], 16;" :: "r"(dst), "l"(src) : "memory");
}
#define CP_COMMIT() asm volatile("cp.async.commit_group;" ::: "memory")
#define CP_WAIT(n)  asm volatile("cp.async.wait_group %0;" :: "n"(n) : "memory")

__device__ __forceinline__ uint32_t f2tf32(float f) {
    uint32_t u;
    asm("cvt.rna.tf32.f32 %0, %1;" : "=r"(u) : "f"(f));
    return u;
}
__device__ __forceinline__ float tf32f(float f) { return __uint_as_float(f2tf32(f)); }

__device__ __forceinline__ void mma_tf32(float c[4],
    uint32_t a0, uint32_t a1, uint32_t a2, uint32_t a3, uint32_t b0, uint32_t b1)
{
    asm volatile("mma.sync.aligned.m16n8k8.row.col.f32.tf32.tf32.f32 "
        "{%0,%1,%2,%3}, {%4,%5,%6,%7}, {%8,%9}, {%0,%1,%2,%3};"
        : "+f"(c[0]), "+f"(c[1]), "+f"(c[2]), "+f"(c[3])
        : "r"(a0), "r"(a1), "r"(a2), "r"(a3), "r"(b0), "r"(b1));
}

// k-pair permutation: within each 8-group store k at position perm8(k),
// so {k, k+4} sit adjacent -> fragment loads become lds.64.
__device__ __forceinline__ int perm8(int r) { return (r < 4) ? (2 * r) : (2 * r - 7); }
__device__ __forceinline__ int pcol(int c) { return (c & ~7) | perm8(c & 7); }

// ---------------- tf32 mma.sync GEMM (validated in R3) ----------------
#define A_STR 36
#define B_STR 136
#define A_CH  (128 * A_STR)
#define B_CH  (32 * B_STR)
#define A_TOT (2 * A_CH)
#define GS_FLOATS (A_TOT + 2 * B_CH)

__global__ __launch_bounds__(256) void gemm_mma(
    const float* __restrict__ W0,
    const float* __restrict__ W1,
    const float* __restrict__ W2,
    const float* __restrict__ Bsrc0,
    int mode)
{
    extern __shared__ float sm[];
    float* As = sm;
    float* Bs = sm + A_TOT;
    const uint32_t sb = smem_u32(sm);

    const int t   = threadIdx.x;
    const int wid = t >> 5;
    const int lane = t & 31;
    const int g  = lane >> 2;
    const int tg = lane & 3;
    const int wm = wid & 1;
    const int wn = wid >> 1;

    const int n0 = blockIdx.x * 128;
    const int y  = blockIdx.y;
    const int b  = blockIdx.z;

    const float* W;
    float* outbuf;
    int o0;
    if (mode == 0) {
        int fam = y / 3;
        o0 = (y % 3) * 128;
        W = (fam == 0) ? W0 : (fam == 1) ? W1 : W2;
        outbuf = (fam == 0) ? g_Q : (fam == 1) ? g_K : g_V;
    } else {
        o0 = y * 128;
        W = W0;
        outbuf = g_P;
    }
    const float* Bp = ((mode == 0) ? Bsrc0 : g_AO) + (size_t)b * C_ * N_;

    float acc[4][4][4];
#pragma unroll
    for (int i = 0; i < 4; i++)
#pragma unroll
        for (int j = 0; j < 4; j++) {
            acc[i][j][0] = 0.f; acc[i][j][1] = 0.f;
            acc[i][j][2] = 0.f; acc[i][j][3] = 0.f;
        }

    auto issue = [&](int kc, int buf) {
        const int k0 = kc * 32;
        uint32_t adst = sb + (uint32_t)(buf * A_CH) * 4u;
        uint32_t bdst = sb + (uint32_t)(A_TOT + buf * B_CH) * 4u;
#pragma unroll
        for (int r = 0; r < 4; r++) {
            int i = t + r * 256;
            int row = i >> 3, c4 = (i & 7) * 4;
            cp16(adst + (uint32_t)(row * A_STR + c4) * 4u,
                 W + (size_t)(o0 + row) * C_ + k0 + c4);
        }
#pragma unroll
        for (int r = 0; r < 4; r++) {
            int i = t + r * 256;
            int row = i >> 5, c4 = (i & 31) * 4;
            cp16(bdst + (uint32_t)(row * B_STR + c4) * 4u,
                 Bp + (size_t)(k0 + row) * N_ + n0 + c4);
        }
    };

    issue(0, 0);
    CP_COMMIT();

    for (int kc = 0; kc < 12; kc++) {
        const int buf = kc & 1;
        if (kc + 1 < 12) {
            issue(kc + 1, buf ^ 1);
            CP_COMMIT();
            CP_WAIT(1);
        } else {
            CP_WAIT(0);
        }
        __syncthreads();

        const float* As_ = As + buf * A_CH;
        const float* Bs_ = Bs + buf * B_CH;

#pragma unroll
        for (int ks = 0; ks < 4; ks++) {
            const int k0 = ks * 8;
            uint32_t af[4][4], bf[4][2];
#pragma unroll
            for (int mt = 0; mt < 4; mt++) {
                const float* ap = As_ + (wm * 64 + mt * 16 + g) * A_STR + k0 + tg;
                af[mt][0] = f2tf32(ap[0]);
                af[mt][1] = f2tf32(ap[8 * A_STR]);
                af[mt][2] = f2tf32(ap[4]);
                af[mt][3] = f2tf32(ap[8 * A_STR + 4]);
            }
#pragma unroll
            for (int nt = 0; nt < 4; nt++) {
                const float* bp = Bs_ + (k0 + tg) * B_STR + wn * 32 + nt * 8 + g;
                bf[nt][0] = f2tf32(bp[0]);
                bf[nt][1] = f2tf32(bp[4 * B_STR]);
            }
#pragma unroll
            for (int mt = 0; mt < 4; mt++)
#pragma unroll
                for (int nt = 0; nt < 4; nt++)
                    mma_tf32(acc[mt][nt], af[mt][0], af[mt][1], af[mt][2], af[mt][3],
                             bf[nt][0], bf[nt][1]);
        }
        __syncthreads();
    }

    float* D = outbuf + (size_t)b * C_ * N_;
#pragma unroll
    for (int mt = 0; mt < 4; mt++) {
        const int o = o0 + wm * 64 + mt * 16 + g;
#pragma unroll
        for (int nt = 0; nt < 4; nt++) {
            const int n = n0 + wn * 32 + nt * 8 + tg * 2;
            *(float2*)(D + (size_t)o * N_ + n)       = make_float2(acc[mt][nt][0], acc[mt][nt][1]);
            *(float2*)(D + (size_t)(o + 8) * N_ + n) = make_float2(acc[mt][nt][2], acc[mt][nt][3]);
        }
    }
}

// ---------------- K2: depthwise 3x3 PE + add (smem tiled) ----------------
__global__ __launch_bounds__(256) void dwconv_smem(const float* __restrict__ Wpe)
{
    __shared__ float tile[34 * 34];
    __shared__ float wsh[9];
    const int bc = blockIdx.x;
    const int c  = bc % C_;
    const float* vb = g_V + (size_t)bc * N_;
    const int t = threadIdx.x;
    if (t < 9) wsh[t] = Wpe[c * 9 + t];
    for (int i = t; i < 34 * 34; i += 256) {
        int r = i / 34 - 1, col = i % 34 - 1;
        tile[i] = (r >= 0 && r < 32 && col >= 0 && col < 32) ? vb[r * 32 + col] : 0.f;
    }
    __syncthreads();
    const float w0 = wsh[0], w1 = wsh[1], w2 = wsh[2];
    const float w3 = wsh[3], w4 = wsh[4], w5 = wsh[5];
    const float w6 = wsh[6], w7 = wsh[7], w8 = wsh[8];
    float* outp = g_V2 + (size_t)bc * N_;
#pragma unroll
    for (int j = 0; j < 4; j++) {
        int n = t + j * 256;
        int hh = n >> 5, ww = n & 31;
        const float* tp = &tile[hh * 34 + ww];
        float s = w0 * tp[0]  + w1 * tp[1]  + w2 * tp[2]
                + w3 * tp[34] + w4 * tp[35] + w5 * tp[36]
                + w6 * tp[68] + w7 * tp[69] + w8 * tp[70];
        outp[n] = tp[35] + s;
    }
}

// ---------------- K3: attention (tf32 mma.sync) ----------------
// One CTA per (be, h, 128-row pair): loads K/V once, two 64-row Q passes.
// smem floats (tf32-prerounded except S):
//   Qs [64][72]   @ 0       (4608)
//   Kt [256][72]  @ 4608    (18432)
//   S  [64][264]  @ 23040   (16896)   fp32 scores -> tf32 P after softmax
//   Vs [64][264]  @ 39936   (16896)
#define QS_STR 72
#define KT_STR 72
#define SS_STR 264
#define VS_STR 264
#define OFF_QS 0
#define OFF_KT 4608
#define OFF_S  23040
#define OFF_VS 39936
#define ATTN_FLOATS 56832   // 227328 bytes

__global__ __launch_bounds__(256, 1) void attn_mma()
{
    extern __shared__ float sm[];
    float* Qs = sm + OFF_QS;
    float* Kt = sm + OFF_KT;
    float* Sc = sm + OFF_S;
    float* Vs = sm + OFF_VS;

    const int pt = blockIdx.x;      // 0..1 (pair of 64-row tiles)
    const int h  = blockIdx.y;      // 0..5
    const int be = blockIdx.z;      // 0..127
    const int b  = be >> 2;
    const int sP = be & 3;

    const int t = threadIdx.x;
    const int wid = t >> 5, lane = t & 31;
    const int g = lane >> 2, tg = lane & 3;
    const int wm = wid & 3;          // 4 row-tiles of 16
    const int wn = wid >> 2;         // 2 col-halves

    const float* Qg = g_Q  + ((size_t)b * C_ + h * HD) * N_ + sP * NE;
    const float* Kg = g_K  + ((size_t)b * C_ + h * HD) * N_ + sP * NE;
    const float* Vg = g_V2 + ((size_t)b * C_ + h * HD) * N_ + sP * NE;

    // ---- load K (transposed, k=d permuted) and V (natural, k=m permuted) ----
    {
        const int d  = t & 63;
        const int q  = t >> 6;       // 0..3
        const int pd = pcol(d);
#pragma unroll
        for (int mb = 0; mb < 16; mb++) {
            int m4 = q * 4 + mb * 16;
            float4 v = *(const float4*)(Kg + (size_t)d * N_ + m4);
            Kt[(m4 + 0) * KT_STR + pd] = tf32f(v.x);
            Kt[(m4 + 1) * KT_STR + pd] = tf32f(v.y);
            Kt[(m4 + 2) * KT_STR + pd] = tf32f(v.z);
            Kt[(m4 + 3) * KT_STR + pd] = tf32f(v.w);
        }
        float* vrow = Vs + d * VS_STR;
#pragma unroll
        for (int mb = 0; mb < 16; mb++) {
            int m4 = q * 4 + mb * 16;
            float4 v = *(const float4*)(Vg + (size_t)d * N_ + m4);
            vrow[pcol(m4 + 0)] = tf32f(v.x);
            vrow[pcol(m4 + 1)] = tf32f(v.y);
            vrow[pcol(m4 + 2)] = tf32f(v.z);
            vrow[pcol(m4 + 3)] = tf32f(v.w);
        }
    }

    for (int pass = 0; pass < 2; pass++) {
        const int n0 = pt * 128 + pass * 64;

        // ---- load Q tile (transposed, k=d permuted) ----
        {
            const int d  = t & 63;
            const int q  = t >> 6;
            const int pd = pcol(d);
#pragma unroll
            for (int nb = 0; nb < 4; nb++) {
                int n4 = q * 4 + nb * 16;
                float4 v = *(const float4*)(Qg + (size_t)d * N_ + n0 + n4);
                Qs[(n4 + 0) * QS_STR + pd] = tf32f(v.x);
                Qs[(n4 + 1) * QS_STR + pd] = tf32f(v.y);
                Qs[(n4 + 2) * QS_STR + pd] = tf32f(v.z);
                Qs[(n4 + 3) * QS_STR + pd] = tf32f(v.w);
            }
        }
        __syncthreads();

        // ---- QK^T: S[64][256] ----
        float acc[16][4];
#pragma unroll
        for (int i = 0; i < 16; i++) {
            acc[i][0] = 0.f; acc[i][1] = 0.f; acc[i][2] = 0.f; acc[i][3] = 0.f;
        }
#pragma unroll
        for (int ks = 0; ks < 8; ks++) {
            const float* ap = Qs + (wm * 16 + g) * QS_STR + ks * 8 + 2 * tg;
            float2 aL = *(const float2*)ap;
            float2 aH = *(const float2*)(ap + 8 * QS_STR);
            uint32_t a0 = __float_as_uint(aL.x), a2 = __float_as_uint(aL.y);
            uint32_t a1 = __float_as_uint(aH.x), a3 = __float_as_uint(aH.y);
#pragma unroll
            for (int nf = 0; nf < 16; nf++) {
                const float* bp = Kt + (wn * 128 + nf * 8 + g) * KT_STR + ks * 8 + 2 * tg;
                float2 bv = *(const float2*)bp;
                mma_tf32(acc[nf], a0, a1, a2, a3,
                         __float_as_uint(bv.x), __float_as_uint(bv.y));
            }
        }
        // store scores (fp32, permuted cols)
        {
            const int r0 = wm * 16 + g;
            const int c0 = perm8(2 * tg), c1 = perm8(2 * tg + 1);
#pragma unroll
            for (int nf = 0; nf < 16; nf++) {
                const int mb = wn * 128 + nf * 8;
                Sc[r0 * SS_STR + mb + c0]       = acc[nf][0];
                Sc[r0 * SS_STR + mb + c1]       = acc[nf][1];
                Sc[(r0 + 8) * SS_STR + mb + c0] = acc[nf][2];
                Sc[(r0 + 8) * SS_STR + mb + c1] = acc[nf][3];
            }
        }
        __syncthreads();

        // ---- softmax (warp per row, 8 rows each); write P as tf32 ----
        {
            const float scale = 0.125f;
#pragma unroll
            for (int rr = 0; rr < 8; rr++) {
                int r = wid * 8 + rr;
                float* row = &Sc[r * SS_STR];
                float vals[8];
                float mx = -1e30f;
#pragma unroll
                for (int j = 0; j < 8; j++) {
                    vals[j] = row[lane + 32 * j] * scale;
                    mx = fmaxf(mx, vals[j]);
                }
#pragma unroll
                for (int o = 16; o > 0; o >>= 1)
                    mx = fmaxf(mx, __shfl_xor_sync(0xffffffffu, mx, o));
                float sum = 0.f;
#pragma unroll
                for (int j = 0; j < 8; j++) {
                    vals[j] = __expf(vals[j] - mx);
                    sum += vals[j];
                }
#pragma unroll
                for (int o = 16; o > 0; o >>= 1)
                    sum += __shfl_xor_sync(0xffffffffu, sum, o);
                float inv = 1.f / sum;
#pragma unroll
                for (int j = 0; j < 8; j++)
                    row[lane + 32 * j] = tf32f(vals[j] * inv);
            }
        }
        __syncthreads();

        // ---- AV: D[64 n][64 d] = P[n][m] * V[m][d] ----
        float av[4][4];
#pragma unroll
        for (int i = 0; i < 4; i++) {
            av[i][0] = 0.f; av[i][1] = 0.f; av[i][2] = 0.f; av[i][3] = 0.f;
        }
#pragma unroll
        for (int ks = 0; ks < 32; ks++) {
            const float* ap = Sc + (wm * 16 + g) * SS_STR + ks * 8 + 2 * tg;
            float2 aL = *(const float2*)ap;
            float2 aH = *(const float2*)(ap + 8 * SS_STR);
            uint32_t a0 = __float_as_uint(aL.x), a2 = __float_as_uint(aL.y);
            uint32_t a1 = __float_as_uint(aH.x), a3 = __float_as_uint(aH.y);
#pragma unroll
            for (int nf = 0; nf < 4; nf++) {
                const float* bp = Vs + (wn * 32 + nf * 8 + g) * VS_STR + ks * 8 + 2 * tg;
                float2 bv = *(const float2*)bp;
                mma_tf32(av[nf], a0, a1, a2, a3,
                         __float_as_uint(bv.x), __float_as_uint(bv.y));
            }
        }

        // ---- scatter to AO[b][cz][nf2] (torch-faithful layout) ----
        {
            float* AOb = g_AO + (size_t)b * C_ * N_;
#pragma unroll
            for (int nf = 0; nf < 4; nf++) {
#pragma unroll
                for (int e = 0; e < 4; e++) {
                    int n = n0 + wm * 16 + g + ((e >> 1) ? 8 : 0);
                    int d = wn * 32 + nf * 8 + 2 * tg + (e & 1);
                    unsigned lin = (unsigned)(h * HD + d) * NE + (unsigned)n;
                    unsigned ne2 = lin / C_;
                    unsigned cz  = lin - ne2 * C_;
                    unsigned nf2 = ne2 * S_ + (unsigned)sP;
                    AOb[(size_t)cz * N_ + nf2] = av[nf][e];
                }
            }
        }
        if (pass == 0) __syncthreads();   // Q reload + S reuse ordering
    }
}

// ---------------- K5: BN stats (deterministic) ----------------
__global__ __launch_bounds__(256) void bn_stats()
{
    const int o = blockIdx.x;
    const int t = threadIdx.x;
    float s = 0.f, sq = 0.f;
    for (int i = t; i < B_ * N_; i += 256) {
        int b = i >> 10, n = i & (N_ - 1);
        float v = g_P[((size_t)b * C_ + o) * N_ + n];
        s  += v;
        sq += v * v;
    }
    __shared__ float rs[256], rq[256];
    rs[t] = s; rq[t] = sq;
    __syncthreads();
    for (int st = 128; st > 0; st >>= 1) {
        if (t < st) { rs[t] += rs[t + st]; rq[t] += rq[t + st]; }
        __syncthreads();
    }
    if (t == 0) {
        float inv_n = 1.f / (float)(B_ * N_);
        float mu  = rs[0] * inv_n;
        float var = rq[0] * inv_n - mu * mu;
        g_mean[o] = mu;
        g_rstd[o] = rsqrtf(var + EPS_);
    }
}

// ---------------- K6: residual + BN normalize ----------------
__global__ __launch_bounds__(256) void final_kernel(
    const float* __restrict__ x,
    const float* __restrict__ gamma,
    const float* __restrict__ beta,
    float* __restrict__ out)
{
    int idx = blockIdx.x * 256 + threadIdx.x;
    int c = (idx / N_) % C_;
    float v = g_P[idx];
    out[idx] = x[idx] + gamma[c] * (v - g_mean[c]) * g_rstd[c] + beta[c];
}

// ---------------- launch ----------------
extern "C" void kernel_launch(void* const* d_in, const int* in_sizes, int n_in,
                              void* d_out, int out_size)
{
    const float* x     = (const float*)d_in[0];
    const float* Wq    = (const float*)d_in[1];
    const float* Wk    = (const float*)d_in[2];
    const float* Wv    = (const float*)d_in[3];
    const float* Wpe   = (const float*)d_in[4];
    const float* Wproj = (const float*)d_in[5];
    const float* gamma = (const float*)d_in[6];
    const float* beta  = (const float*)d_in[7];
    float* out = (float*)d_out;

    static bool attr_set = false;
    if (!attr_set) {
        cudaFuncSetAttribute(gemm_mma, cudaFuncAttributeMaxDynamicSharedMemorySize,
                             GS_FLOATS * (int)sizeof(float));
        cudaFuncSetAttribute(attn_mma, cudaFuncAttributeMaxDynamicSharedMemorySize,
                             ATTN_FLOATS * (int)sizeof(float));
        attr_set = true;
    }

    gemm_mma<<<dim3(N_ / 128, 9, B_), 256, GS_FLOATS * sizeof(float)>>>(Wq, Wk, Wv, x, 0);

    dwconv_smem<<<B_ * C_, 256>>>(Wpe);

    attn_mma<<<dim3(2, NHEAD, 128), 256, ATTN_FLOATS * sizeof(float)>>>();

    gemm_mma<<<dim3(N_ / 128, 3, B_), 256, GS_FLOATS * sizeof(float)>>>(Wproj, Wproj, Wproj, nullptr, 1);

    bn_stats<<<C_, 256>>>();

    final_kernel<<<(B_ * C_ * N_) / 256, 256>>>(x, gamma, beta, out);
}

// round 5
// speedup vs baseline: 3.1420x; 1.1428x over previous
#include <cuda_runtime.h>
#include <math.h>
#include <stdint.h>

#define B_    32
#define C_    384
#define Hh    32
#define Ww    32
#define N_    1024
#define S_    4
#define NE    256
#define NHEAD 6
#define HD    64
#define EPS_  1e-5f

// ---------------- scratch (device globals; no allocation) ----------------
__device__ float g_Q [B_*C_*N_];   // [b][c][n]
__device__ float g_K [B_*C_*N_];
__device__ float g_V [B_*C_*N_];
__device__ float g_V2[B_*C_*N_];
__device__ float g_AO[B_*N_*C_];   // attention output [b][nf][cz]  (k-contig for NT proj)
__device__ float g_P [B_*C_*N_];   // proj output [b][c][n]
__device__ float g_mean[C_];
__device__ float g_rstd[C_];

// ---------------- generic-PTX helpers ----------------
__device__ __forceinline__ uint32_t smem_u32(const void* p) {
    uint32_t a;
    asm("{ .reg .u64 t; cvta.to.shared.u64 t, %1; cvt.u32.u64 %0, t; }" : "=r"(a) : "l"(p));
    return a;
}
__device__ __forceinline__ void cp16(uint32_t dst, const void* src) {
    asm volatile("cp.async.cg.shared.global [%0], [%1], 16;" :: "r"(dst), "l"(src) : "memory");
}
#define CP_COMMIT() asm volatile("cp.async.commit_group;" ::: "memory")
#define CP_WAIT(n)  asm volatile("cp.async.wait_group %0;" :: "n"(n) : "memory")

__device__ __forceinline__ uint32_t f2tf32(float f) {
    uint32_t u;
    asm("cvt.rna.tf32.f32 %0, %1;" : "=r"(u) : "f"(f));
    return u;
}
__device__ __forceinline__ float tf32f(float f) { return __uint_as_float(f2tf32(f)); }

__device__ __forceinline__ void mma_tf32(float c[4],
    uint32_t a0, uint32_t a1, uint32_t a2, uint32_t a3, uint32_t b0, uint32_t b1)
{
    asm volatile("mma.sync.aligned.m16n8k8.row.col.f32.tf32.tf32.f32 "
        "{%0,%1,%2,%3}, {%4,%5,%6,%7}, {%8,%9}, {%0,%1,%2,%3};"
        : "+f"(c[0]), "+f"(c[1]), "+f"(c[2]), "+f"(c[3])
        : "r"(a0), "r"(a1), "r"(a2), "r"(a3), "r"(b0), "r"(b1));
}

// k-pair permutation: within each 8-group, {k, k+4} become adjacent -> lds.64 A-frags
__device__ __forceinline__ int perm8(int r) { return (r < 4) ? (2 * r) : (2 * r - 7); }
__device__ __forceinline__ int pcol(int c) { return (c & ~7) | perm8(c & 7); }

// ---------------- K1: QKV tf32 GEMM (NN: B = x[b][c][n]) ----------------
#define A_STR 36
#define B_STR 136
#define A_CH  (128 * A_STR)
#define B_CH  (32 * B_STR)
#define A_TOT (2 * A_CH)
#define GS_FLOATS (A_TOT + 2 * B_CH)

__global__ __launch_bounds__(256) void qkv_mma(
    const float* __restrict__ Wq,
    const float* __restrict__ Wk,
    const float* __restrict__ Wv,
    const float* __restrict__ x)
{
    extern __shared__ float sm[];
    float* As = sm;
    float* Bs = sm + A_TOT;
    const uint32_t sb = smem_u32(sm);

    const int t   = threadIdx.x;
    const int wid = t >> 5;
    const int lane = t & 31;
    const int g  = lane >> 2;
    const int tg = lane & 3;
    const int wm = wid & 1;
    const int wn = wid >> 1;

    const int n0 = blockIdx.x * 128;
    const int y  = blockIdx.y;
    const int b  = blockIdx.z;

    const int fam = y / 3;
    const int o0 = (y % 3) * 128;
    const float* W = (fam == 0) ? Wq : (fam == 1) ? Wk : Wv;
    float* outbuf = (fam == 0) ? g_Q : (fam == 1) ? g_K : g_V;
    const float* Bp = x + (size_t)b * C_ * N_;

    float acc[4][4][4];
#pragma unroll
    for (int i = 0; i < 4; i++)
#pragma unroll
        for (int j = 0; j < 4; j++) {
            acc[i][j][0] = 0.f; acc[i][j][1] = 0.f;
            acc[i][j][2] = 0.f; acc[i][j][3] = 0.f;
        }

    auto issue = [&](int kc, int buf) {
        const int k0 = kc * 32;
        uint32_t adst = sb + (uint32_t)(buf * A_CH) * 4u;
        uint32_t bdst = sb + (uint32_t)(A_TOT + buf * B_CH) * 4u;
#pragma unroll
        for (int r = 0; r < 4; r++) {
            int i = t + r * 256;
            int row = i >> 3, c4 = (i & 7) * 4;
            cp16(adst + (uint32_t)(row * A_STR + c4) * 4u,
                 W + (size_t)(o0 + row) * C_ + k0 + c4);
        }
#pragma unroll
        for (int r = 0; r < 4; r++) {
            int i = t + r * 256;
            int row = i >> 5, c4 = (i & 31) * 4;
            cp16(bdst + (uint32_t)(row * B_STR + c4) * 4u,
                 Bp + (size_t)(k0 + row) * N_ + n0 + c4);
        }
    };

    issue(0, 0);
    CP_COMMIT();

    for (int kc = 0; kc < 12; kc++) {
        const int buf = kc & 1;
        if (kc + 1 < 12) {
            issue(kc + 1, buf ^ 1);
            CP_COMMIT();
            CP_WAIT(1);
        } else {
            CP_WAIT(0);
        }
        __syncthreads();

        const float* As_ = As + buf * A_CH;
        const float* Bs_ = Bs + buf * B_CH;

#pragma unroll
        for (int ks = 0; ks < 4; ks++) {
            const int k0 = ks * 8;
            uint32_t af[4][4], bf[4][2];
#pragma unroll
            for (int mt = 0; mt < 4; mt++) {
                const float* ap = As_ + (wm * 64 + mt * 16 + g) * A_STR + k0 + tg;
                af[mt][0] = f2tf32(ap[0]);
                af[mt][1] = f2tf32(ap[8 * A_STR]);
                af[mt][2] = f2tf32(ap[4]);
                af[mt][3] = f2tf32(ap[8 * A_STR + 4]);
            }
#pragma unroll
            for (int nt = 0; nt < 4; nt++) {
                const float* bp = Bs_ + (k0 + tg) * B_STR + wn * 32 + nt * 8 + g;
                bf[nt][0] = f2tf32(bp[0]);
                bf[nt][1] = f2tf32(bp[4 * B_STR]);
            }
#pragma unroll
            for (int mt = 0; mt < 4; mt++)
#pragma unroll
                for (int nt = 0; nt < 4; nt++)
                    mma_tf32(acc[mt][nt], af[mt][0], af[mt][1], af[mt][2], af[mt][3],
                             bf[nt][0], bf[nt][1]);
        }
        __syncthreads();
    }

    float* D = outbuf + (size_t)b * C_ * N_;
#pragma unroll
    for (int mt = 0; mt < 4; mt++) {
        const int o = o0 + wm * 64 + mt * 16 + g;
#pragma unroll
        for (int nt = 0; nt < 4; nt++) {
            const int n = n0 + wn * 32 + nt * 8 + tg * 2;
            *(float2*)(D + (size_t)o * N_ + n)       = make_float2(acc[mt][nt][0], acc[mt][nt][1]);
            *(float2*)(D + (size_t)(o + 8) * N_ + n) = make_float2(acc[mt][nt][2], acc[mt][nt][3]);
        }
    }
}

// ---------------- K4: proj tf32 GEMM (NT: B = AO[b][nf][cz], k-contig) ----------------
#define P_CH (128 * A_STR)           // 4608 floats per tile buffer
#define PS_FLOATS (4 * P_CH)         // A double + B double = 18432 floats

__global__ __launch_bounds__(256) void proj_mma(const float* __restrict__ Wp)
{
    extern __shared__ float sm[];
    float* As = sm;
    float* Bs = sm + 2 * P_CH;
    const uint32_t sb = smem_u32(sm);

    const int t   = threadIdx.x;
    const int wid = t >> 5;
    const int lane = t & 31;
    const int g  = lane >> 2;
    const int tg = lane & 3;
    const int wm = wid & 1;
    const int wn = wid >> 1;

    const int n0 = blockIdx.x * 128;
    const int o0 = blockIdx.y * 128;
    const int b  = blockIdx.z;

    const float* Bp = g_AO + (size_t)b * N_ * C_;   // [nf][cz]

    float acc[4][4][4];
#pragma unroll
    for (int i = 0; i < 4; i++)
#pragma unroll
        for (int j = 0; j < 4; j++) {
            acc[i][j][0] = 0.f; acc[i][j][1] = 0.f;
            acc[i][j][2] = 0.f; acc[i][j][3] = 0.f;
        }

    auto issue = [&](int kc, int buf) {
        const int k0 = kc * 32;
        uint32_t adst = sb + (uint32_t)(buf * P_CH) * 4u;
        uint32_t bdst = sb + (uint32_t)((2 + buf) * P_CH) * 4u;
#pragma unroll
        for (int r = 0; r < 4; r++) {
            int i = t + r * 256;
            int row = i >> 3, c4 = (i & 7) * 4;
            cp16(adst + (uint32_t)(row * A_STR + c4) * 4u,
                 Wp + (size_t)(o0 + row) * C_ + k0 + c4);
            cp16(bdst + (uint32_t)(row * A_STR + c4) * 4u,
                 Bp + (size_t)(n0 + row) * C_ + k0 + c4);
        }
    };

    issue(0, 0);
    CP_COMMIT();

    for (int kc = 0; kc < 12; kc++) {
        const int buf = kc & 1;
        if (kc + 1 < 12) {
            issue(kc + 1, buf ^ 1);
            CP_COMMIT();
            CP_WAIT(1);
        } else {
            CP_WAIT(0);
        }
        __syncthreads();

        const float* As_ = As + buf * P_CH;
        const float* Bs_ = Bs + buf * P_CH;

#pragma unroll
        for (int ks = 0; ks < 4; ks++) {
            const int k0 = ks * 8;
            uint32_t af[4][4], bf[4][2];
#pragma unroll
            for (int mt = 0; mt < 4; mt++) {
                const float* ap = As_ + (wm * 64 + mt * 16 + g) * A_STR + k0 + tg;
                af[mt][0] = f2tf32(ap[0]);
                af[mt][1] = f2tf32(ap[8 * A_STR]);
                af[mt][2] = f2tf32(ap[4]);
                af[mt][3] = f2tf32(ap[8 * A_STR + 4]);
            }
#pragma unroll
            for (int nt = 0; nt < 4; nt++) {
                const float* bp = Bs_ + (wn * 32 + nt * 8 + g) * A_STR + k0 + tg;
                bf[nt][0] = f2tf32(bp[0]);
                bf[nt][1] = f2tf32(bp[4]);
            }
#pragma unroll
            for (int mt = 0; mt < 4; mt++)
#pragma unroll
                for (int nt = 0; nt < 4; nt++)
                    mma_tf32(acc[mt][nt], af[mt][0], af[mt][1], af[mt][2], af[mt][3],
                             bf[nt][0], bf[nt][1]);
        }
        __syncthreads();
    }

    float* D = g_P + (size_t)b * C_ * N_;
#pragma unroll
    for (int mt = 0; mt < 4; mt++) {
        const int o = o0 + wm * 64 + mt * 16 + g;
#pragma unroll
        for (int nt = 0; nt < 4; nt++) {
            const int n = n0 + wn * 32 + nt * 8 + tg * 2;
            *(float2*)(D + (size_t)o * N_ + n)       = make_float2(acc[mt][nt][0], acc[mt][nt][1]);
            *(float2*)(D + (size_t)(o + 8) * N_ + n) = make_float2(acc[mt][nt][2], acc[mt][nt][3]);
        }
    }
}

// ---------------- K2: depthwise 3x3 PE + add (smem tiled) ----------------
__global__ __launch_bounds__(256) void dwconv_smem(const float* __restrict__ Wpe)
{
    __shared__ float tile[34 * 34];
    __shared__ float wsh[9];
    const int bc = blockIdx.x;
    const int c  = bc % C_;
    const float* vb = g_V + (size_t)bc * N_;
    const int t = threadIdx.x;
    if (t < 9) wsh[t] = Wpe[c * 9 + t];
    for (int i = t; i < 34 * 34; i += 256) {
        int r = i / 34 - 1, col = i % 34 - 1;
        tile[i] = (r >= 0 && r < 32 && col >= 0 && col < 32) ? vb[r * 32 + col] : 0.f;
    }
    __syncthreads();
    const float w0 = wsh[0], w1 = wsh[1], w2 = wsh[2];
    const float w3 = wsh[3], w4 = wsh[4], w5 = wsh[5];
    const float w6 = wsh[6], w7 = wsh[7], w8 = wsh[8];
    float* outp = g_V2 + (size_t)bc * N_;
#pragma unroll
    for (int j = 0; j < 4; j++) {
        int n = t + j * 256;
        int hh = n >> 5, ww = n & 31;
        const float* tp = &tile[hh * 34 + ww];
        float s = w0 * tp[0]  + w1 * tp[1]  + w2 * tp[2]
                + w3 * tp[34] + w4 * tp[35] + w5 * tp[36]
                + w6 * tp[68] + w7 * tp[69] + w8 * tp[70];
        outp[n] = tp[35] + s;
    }
}

// ---------------- K3: attention (tf32 mma.sync, coalesced, K/V loaded once) ----------------
// One CTA per (h, be). 256 threads. 4 passes of 64 Q-rows.
// smem floats:
//   Ks [64 d][264 m]  @ 0      (16896)   raw fp32, cp.async
//   Vs [64 d][260 m]  @ 16896  (16640)   raw fp32, cp.async
//   Qs [64 n][72 d]   @ 33536  (4608)    tf32-rounded, d pair-permuted
//   Sc [64 n][264 m]  @ 38144  (16896)   scores fp32 -> P tf32, m pair-permuted
#define KS_STR 264
#define VS_STR 260
#define QS_STR 72
#define SS_STR 264
#define OFF_KS 0
#define OFF_VS 16896
#define OFF_QS 33536
#define OFF_SC 38144
#define ATTN_FLOATS 55040   // 220160 bytes

__global__ __launch_bounds__(256, 1) void attn_mma()
{
    extern __shared__ float sm[];
    float* Ks = sm + OFF_KS;
    float* Vs = sm + OFF_VS;
    float* Qs = sm + OFF_QS;
    float* Sc = sm + OFF_SC;
    const uint32_t ks_b = smem_u32(Ks);
    const uint32_t vs_b = smem_u32(Vs);

    const int h  = blockIdx.x;      // 0..5
    const int be = blockIdx.y;      // 0..127
    const int b  = be >> 2;
    const int sP = be & 3;

    const int t = threadIdx.x;
    const int wid = t >> 5, lane = t & 31;
    const int g = lane >> 2, tg = lane & 3;
    const int wm = wid & 3;          // 4 row-tiles of 16
    const int wn = wid >> 2;         // 2 col-halves

    const float* Qg = g_Q  + ((size_t)b * C_ + h * HD) * N_ + sP * NE;
    const float* Kg = g_K  + ((size_t)b * C_ + h * HD) * N_ + sP * NE;
    const float* Vg = g_V2 + ((size_t)b * C_ + h * HD) * N_ + sP * NE;

    // ---- cp.async load K, V (natural [d][m], coalesced) ----
#pragma unroll
    for (int j = 0; j < 16; j++) {
        int u = t + j * 256;                 // 4096 float4 units
        int d = u >> 6, m4 = (u & 63) * 4;
        cp16(ks_b + (uint32_t)(d * KS_STR + m4) * 4u, Kg + (size_t)d * N_ + m4);
    }
#pragma unroll
    for (int j = 0; j < 16; j++) {
        int u = t + j * 256;
        int d = u >> 6, m4 = (u & 63) * 4;
        cp16(vs_b + (uint32_t)(d * VS_STR + m4) * 4u, Vg + (size_t)d * N_ + m4);
    }
    CP_COMMIT();

    const int c0p = perm8(2 * tg), c1p = perm8(2 * tg + 1);
    float* AOb = g_AO + (size_t)b * N_ * C_;

    for (int pass = 0; pass < 4; pass++) {
        const int n0 = pass * 64;

        // ---- Q transform: [d][n] -> Qs[n][pcol(d)], tf32-rounded ----
#pragma unroll
        for (int j = 0; j < 4; j++) {
            int u = t + j * 256;             // 1024 units: 64 d x 16 n4
            int d = u >> 4, n4 = (u & 15) * 4;
            float4 v = *(const float4*)(Qg + (size_t)d * N_ + n0 + n4);
            int pd = pcol(d);
            Qs[(n4 + 0) * QS_STR + pd] = tf32f(v.x);
            Qs[(n4 + 1) * QS_STR + pd] = tf32f(v.y);
            Qs[(n4 + 2) * QS_STR + pd] = tf32f(v.z);
            Qs[(n4 + 3) * QS_STR + pd] = tf32f(v.w);
        }
        if (pass == 0) { CP_WAIT(0); }
        __syncthreads();   // Qs ready; prior pass AV reads of Sc done

        // ---- QK^T ----
        float acc[16][4];
#pragma unroll
        for (int i = 0; i < 16; i++) {
            acc[i][0] = 0.f; acc[i][1] = 0.f; acc[i][2] = 0.f; acc[i][3] = 0.f;
        }
#pragma unroll
        for (int ks = 0; ks < 8; ks++) {
            const float* ap = Qs + (wm * 16 + g) * QS_STR + ks * 8 + 2 * tg;
            float2 aL = *(const float2*)ap;
            float2 aH = *(const float2*)(ap + 8 * QS_STR);
            uint32_t a0 = __float_as_uint(aL.x), a2 = __float_as_uint(aL.y);
            uint32_t a1 = __float_as_uint(aH.x), a3 = __float_as_uint(aH.y);
#pragma unroll
            for (int nf = 0; nf < 16; nf++) {
                const float* bp = Ks + (ks * 8 + tg) * KS_STR + wn * 128 + nf * 8 + g;
                uint32_t b0 = f2tf32(bp[0]);
                uint32_t b1 = f2tf32(bp[4 * KS_STR]);
                mma_tf32(acc[nf], a0, a1, a2, a3, b0, b1);
            }
        }
        {
            const int r0 = wm * 16 + g;
#pragma unroll
            for (int nf = 0; nf < 16; nf++) {
                const int mb = wn * 128 + nf * 8;
                Sc[r0 * SS_STR + mb + c0p]       = acc[nf][0];
                Sc[r0 * SS_STR + mb + c1p]       = acc[nf][1];
                Sc[(r0 + 8) * SS_STR + mb + c0p] = acc[nf][2];
                Sc[(r0 + 8) * SS_STR + mb + c1p] = acc[nf][3];
            }
        }
        __syncthreads();

        // ---- softmax (warp per 8 rows); write P as tf32 in-place ----
        {
            const float scale = 0.125f;
#pragma unroll
            for (int rr = 0; rr < 8; rr++) {
                int r = wid * 8 + rr;
                float* row = &Sc[r * SS_STR];
                float vals[8];
                float mx = -1e30f;
#pragma unroll
                for (int j = 0; j < 8; j++) {
                    vals[j] = row[lane + 32 * j] * scale;
                    mx = fmaxf(mx, vals[j]);
                }
#pragma unroll
                for (int o = 16; o > 0; o >>= 1)
                    mx = fmaxf(mx, __shfl_xor_sync(0xffffffffu, mx, o));
                float sum = 0.f;
#pragma unroll
                for (int j = 0; j < 8; j++) {
                    vals[j] = __expf(vals[j] - mx);
                    sum += vals[j];
                }
#pragma unroll
                for (int o = 16; o > 0; o >>= 1)
                    sum += __shfl_xor_sync(0xffffffffu, sum, o);
                float inv = 1.f / sum;
#pragma unroll
                for (int j = 0; j < 8; j++)
                    row[lane + 32 * j] = tf32f(vals[j] * inv);
            }
        }
        __syncthreads();

        // ---- AV ----
        float av[4][4];
#pragma unroll
        for (int i = 0; i < 4; i++) {
            av[i][0] = 0.f; av[i][1] = 0.f; av[i][2] = 0.f; av[i][3] = 0.f;
        }
#pragma unroll
        for (int ks = 0; ks < 32; ks++) {
            const float* ap = Sc + (wm * 16 + g) * SS_STR + ks * 8 + 2 * tg;
            float2 aL = *(const float2*)ap;
            float2 aH = *(const float2*)(ap + 8 * SS_STR);
            uint32_t a0 = __float_as_uint(aL.x), a2 = __float_as_uint(aL.y);
            uint32_t a1 = __float_as_uint(aH.x), a3 = __float_as_uint(aH.y);
#pragma unroll
            for (int nf = 0; nf < 4; nf++) {
                const float* bp = Vs + (wn * 32 + nf * 8 + g) * VS_STR + ks * 8 + tg;
                uint32_t b0 = f2tf32(bp[0]);
                uint32_t b1 = f2tf32(bp[4]);
                mma_tf32(av[nf], a0, a1, a2, a3, b0, b1);
            }
        }

        // ---- store to AO[b][nf2][cz]: 8-lane contiguous cz runs ----
#pragma unroll
        for (int nf = 0; nf < 4; nf++) {
#pragma unroll
            for (int e = 0; e < 4; e++) {
                int n = n0 + wm * 16 + g + ((e >> 1) ? 8 : 0);
                int d = wn * 32 + nf * 8 + 2 * tg + (e & 1);
                unsigned lin = (unsigned)(h * HD + d) * NE + (unsigned)n;
                unsigned ne2 = lin / C_;
                unsigned cz  = lin - ne2 * C_;
                unsigned nf2 = ne2 * S_ + (unsigned)sP;
                AOb[(size_t)nf2 * C_ + cz] = av[nf][e];
            }
        }
        // next pass's first __syncthreads protects Qs/Sc reuse
    }
}

// ---------------- K5: BN stats (deterministic, float4) ----------------
__global__ __launch_bounds__(256) void bn_stats()
{
    const int o = blockIdx.x;
    const int t = threadIdx.x;
    float s = 0.f, sq = 0.f;
#pragma unroll 4
    for (int k = 0; k < 32; k++) {
        int u = t + k * 256;             // 8192 float4 units over [B][N]
        int b = u >> 8, n4 = (u & 255) * 4;
        float4 v = *(const float4*)(g_P + ((size_t)b * C_ + o) * N_ + n4);
        s  += v.x + v.y + v.z + v.w;
        sq += v.x * v.x + v.y * v.y + v.z * v.z + v.w * v.w;
    }
    __shared__ float rs[256], rq[256];
    rs[t] = s; rq[t] = sq;
    __syncthreads();
    for (int st = 128; st > 0; st >>= 1) {
        if (t < st) { rs[t] += rs[t + st]; rq[t] += rq[t + st]; }
        __syncthreads();
    }
    if (t == 0) {
        float inv_n = 1.f / (float)(B_ * N_);
        float mu  = rs[0] * inv_n;
        float var = rq[0] * inv_n - mu * mu;
        g_mean[o] = mu;
        g_rstd[o] = rsqrtf(var + EPS_);
    }
}

// ---------------- K6: residual + BN normalize (float4) ----------------
__global__ __launch_bounds__(256) void final_kernel(
    const float* __restrict__ x,
    const float* __restrict__ gamma,
    const float* __restrict__ beta,
    float* __restrict__ out)
{
    int idx = (blockIdx.x * 256 + threadIdx.x) * 4;
    int c = (idx / N_) % C_;
    float ga = gamma[c], be = beta[c], mu = g_mean[c], rs = g_rstd[c];
    float4 v = *(const float4*)(g_P + idx);
    float4 xv = *(const float4*)(x + idx);
    float4 r;
    r.x = xv.x + ga * (v.x - mu) * rs + be;
    r.y = xv.y + ga * (v.y - mu) * rs + be;
    r.z = xv.z + ga * (v.z - mu) * rs + be;
    r.w = xv.w + ga * (v.w - mu) * rs + be;
    *(float4*)(out + idx) = r;
}

// ---------------- launch ----------------
extern "C" void kernel_launch(void* const* d_in, const int* in_sizes, int n_in,
                              void* d_out, int out_size)
{
    const float* x     = (const float*)d_in[0];
    const float* Wq    = (const float*)d_in[1];
    const float* Wk    = (const float*)d_in[2];
    const float* Wv    = (const float*)d_in[3];
    const float* Wpe   = (const float*)d_in[4];
    const float* Wproj = (const float*)d_in[5];
    const float* gamma = (const float*)d_in[6];
    const float* beta  = (const float*)d_in[7];
    float* out = (float*)d_out;

    static bool attr_set = false;
    if (!attr_set) {
        cudaFuncSetAttribute(qkv_mma, cudaFuncAttributeMaxDynamicSharedMemorySize,
                             GS_FLOATS * (int)sizeof(float));
        cudaFuncSetAttribute(proj_mma, cudaFuncAttributeMaxDynamicSharedMemorySize,
                             PS_FLOATS * (int)sizeof(float));
        cudaFuncSetAttribute(attn_mma, cudaFuncAttributeMaxDynamicSharedMemorySize,
                             ATTN_FLOATS * (int)sizeof(float));
        attr_set = true;
    }

    qkv_mma<<<dim3(N_ / 128, 9, B_), 256, GS_FLOATS * sizeof(float)>>>(Wq, Wk, Wv, x);

    dwconv_smem<<<B_ * C_, 256>>>(Wpe);

    attn_mma<<<dim3(NHEAD, 128), 256, ATTN_FLOATS * sizeof(float)>>>();

    proj_mma<<<dim3(N_ / 128, C_ / 128, B_), 256, PS_FLOATS * sizeof(float)>>>(Wproj);

    bn_stats<<<C_, 256>>>();

    final_kernel<<<(B_ * C_ * N_) / 1024, 256>>>(x, gamma, beta, out);
}

// round 6
// speedup vs baseline: 3.3102x; 1.0535x over previous
#include <cuda_runtime.h>
#include <math.h>
#include <stdint.h>

#define B_    32
#define C_    384
#define Hh    32
#define Ww    32
#define N_    1024
#define S_    4
#define NE    256
#define NHEAD 6
#define HD    64
#define EPS_  1e-5f

// ---------------- scratch (device globals; no allocation) ----------------
__device__ float g_Q [B_*C_*N_];   // [b][c][n]
__device__ float g_K [B_*C_*N_];
__device__ float g_V [B_*C_*N_];   // raw v (pe fused into attention load)
__device__ float g_AO[B_*N_*C_];   // attention output [b][nf][cz]
__device__ float g_P [B_*C_*N_];   // proj output [b][c][n]
__device__ float g_mean[C_];
__device__ float g_rstd[C_];

// ---------------- generic-PTX helpers ----------------
__device__ __forceinline__ uint32_t smem_u32(const void* p) {
    uint32_t a;
    asm("{ .reg .u64 t; cvta.to.shared.u64 t, %1; cvt.u32.u64 %0, t; }" : "=r"(a) : "l"(p));
    return a;
}
__device__ __forceinline__ void cp16(uint32_t dst, const void* src) {
    asm volatile("cp.async.cg.shared.global [%0], [%1], 16;" :: "r"(dst), "l"(src) : "memory");
}
#define CP_COMMIT() asm volatile("cp.async.commit_group;" ::: "memory")
#define CP_WAIT(n)  asm volatile("cp.async.wait_group %0;" :: "n"(n) : "memory")

__device__ __forceinline__ uint32_t f2tf32(float f) {
    uint32_t u;
    asm("cvt.rna.tf32.f32 %0, %1;" : "=r"(u) : "f"(f));
    return u;
}
__device__ __forceinline__ float tf32f(float f) { return __uint_as_float(f2tf32(f)); }

__device__ __forceinline__ void mma_tf32(float c[4],
    uint32_t a0, uint32_t a1, uint32_t a2, uint32_t a3, uint32_t b0, uint32_t b1)
{
    asm volatile("mma.sync.aligned.m16n8k8.row.col.f32.tf32.tf32.f32 "
        "{%0,%1,%2,%3}, {%4,%5,%6,%7}, {%8,%9}, {%0,%1,%2,%3};"
        : "+f"(c[0]), "+f"(c[1]), "+f"(c[2]), "+f"(c[3])
        : "r"(a0), "r"(a1), "r"(a2), "r"(a3), "r"(b0), "r"(b1));
}

// k-pair permutation: {k, k+4} adjacent -> lds.64 A-frags
__device__ __forceinline__ int perm8(int r) { return (r < 4) ? (2 * r) : (2 * r - 7); }
__device__ __forceinline__ int pcol(int c) { return (c & ~7) | perm8(c & 7); }

// ---------------- K1: QKV tf32 GEMM (NN) ----------------
#define A_STR 36
#define B_STR 136
#define A_CH  (128 * A_STR)
#define B_CH  (32 * B_STR)
#define A_TOT (2 * A_CH)
#define GS_FLOATS (A_TOT + 2 * B_CH)

__global__ __launch_bounds__(256) void qkv_mma(
    const float* __restrict__ Wq,
    const float* __restrict__ Wk,
    const float* __restrict__ Wv,
    const float* __restrict__ x)
{
    extern __shared__ float sm[];
    float* As = sm;
    float* Bs = sm + A_TOT;
    const uint32_t sb = smem_u32(sm);

    const int t   = threadIdx.x;
    const int wid = t >> 5;
    const int lane = t & 31;
    const int g  = lane >> 2;
    const int tg = lane & 3;
    const int wm = wid & 1;
    const int wn = wid >> 1;

    const int n0 = blockIdx.x * 128;
    const int y  = blockIdx.y;
    const int b  = blockIdx.z;

    const int fam = y / 3;
    const int o0 = (y % 3) * 128;
    const float* W = (fam == 0) ? Wq : (fam == 1) ? Wk : Wv;
    float* outbuf = (fam == 0) ? g_Q : (fam == 1) ? g_K : g_V;
    const float* Bp = x + (size_t)b * C_ * N_;

    float acc[4][4][4];
#pragma unroll
    for (int i = 0; i < 4; i++)
#pragma unroll
        for (int j = 0; j < 4; j++) {
            acc[i][j][0] = 0.f; acc[i][j][1] = 0.f;
            acc[i][j][2] = 0.f; acc[i][j][3] = 0.f;
        }

    auto issue = [&](int kc, int buf) {
        const int k0 = kc * 32;
        uint32_t adst = sb + (uint32_t)(buf * A_CH) * 4u;
        uint32_t bdst = sb + (uint32_t)(A_TOT + buf * B_CH) * 4u;
#pragma unroll
        for (int r = 0; r < 4; r++) {
            int i = t + r * 256;
            int row = i >> 3, c4 = (i & 7) * 4;
            cp16(adst + (uint32_t)(row * A_STR + c4) * 4u,
                 W + (size_t)(o0 + row) * C_ + k0 + c4);
        }
#pragma unroll
        for (int r = 0; r < 4; r++) {
            int i = t + r * 256;
            int row = i >> 5, c4 = (i & 31) * 4;
            cp16(bdst + (uint32_t)(row * B_STR + c4) * 4u,
                 Bp + (size_t)(k0 + row) * N_ + n0 + c4);
        }
    };

    issue(0, 0);
    CP_COMMIT();

    for (int kc = 0; kc < 12; kc++) {
        const int buf = kc & 1;
        if (kc + 1 < 12) {
            issue(kc + 1, buf ^ 1);
            CP_COMMIT();
            CP_WAIT(1);
        } else {
            CP_WAIT(0);
        }
        __syncthreads();

        const float* As_ = As + buf * A_CH;
        const float* Bs_ = Bs + buf * B_CH;

#pragma unroll
        for (int ks = 0; ks < 4; ks++) {
            const int k0 = ks * 8;
            uint32_t af[4][4], bf[4][2];
#pragma unroll
            for (int mt = 0; mt < 4; mt++) {
                const float* ap = As_ + (wm * 64 + mt * 16 + g) * A_STR + k0 + tg;
                af[mt][0] = f2tf32(ap[0]);
                af[mt][1] = f2tf32(ap[8 * A_STR]);
                af[mt][2] = f2tf32(ap[4]);
                af[mt][3] = f2tf32(ap[8 * A_STR + 4]);
            }
#pragma unroll
            for (int nt = 0; nt < 4; nt++) {
                const float* bp = Bs_ + (k0 + tg) * B_STR + wn * 32 + nt * 8 + g;
                bf[nt][0] = f2tf32(bp[0]);
                bf[nt][1] = f2tf32(bp[4 * B_STR]);
            }
#pragma unroll
            for (int mt = 0; mt < 4; mt++)
#pragma unroll
                for (int nt = 0; nt < 4; nt++)
                    mma_tf32(acc[mt][nt], af[mt][0], af[mt][1], af[mt][2], af[mt][3],
                             bf[nt][0], bf[nt][1]);
        }
        __syncthreads();
    }

    float* D = outbuf + (size_t)b * C_ * N_;
#pragma unroll
    for (int mt = 0; mt < 4; mt++) {
        const int o = o0 + wm * 64 + mt * 16 + g;
#pragma unroll
        for (int nt = 0; nt < 4; nt++) {
            const int n = n0 + wn * 32 + nt * 8 + tg * 2;
            *(float2*)(D + (size_t)o * N_ + n)       = make_float2(acc[mt][nt][0], acc[mt][nt][1]);
            *(float2*)(D + (size_t)(o + 8) * N_ + n) = make_float2(acc[mt][nt][2], acc[mt][nt][3]);
        }
    }
}

// ---------------- K4: proj tf32 GEMM (NT) ----------------
#define P_CH (128 * A_STR)
#define PS_FLOATS (4 * P_CH)

__global__ __launch_bounds__(256) void proj_mma(const float* __restrict__ Wp)
{
    extern __shared__ float sm[];
    float* As = sm;
    float* Bs = sm + 2 * P_CH;
    const uint32_t sb = smem_u32(sm);

    const int t   = threadIdx.x;
    const int wid = t >> 5;
    const int lane = t & 31;
    const int g  = lane >> 2;
    const int tg = lane & 3;
    const int wm = wid & 1;
    const int wn = wid >> 1;

    const int n0 = blockIdx.x * 128;
    const int o0 = blockIdx.y * 128;
    const int b  = blockIdx.z;

    const float* Bp = g_AO + (size_t)b * N_ * C_;

    float acc[4][4][4];
#pragma unroll
    for (int i = 0; i < 4; i++)
#pragma unroll
        for (int j = 0; j < 4; j++) {
            acc[i][j][0] = 0.f; acc[i][j][1] = 0.f;
            acc[i][j][2] = 0.f; acc[i][j][3] = 0.f;
        }

    auto issue = [&](int kc, int buf) {
        const int k0 = kc * 32;
        uint32_t adst = sb + (uint32_t)(buf * P_CH) * 4u;
        uint32_t bdst = sb + (uint32_t)((2 + buf) * P_CH) * 4u;
#pragma unroll
        for (int r = 0; r < 4; r++) {
            int i = t + r * 256;
            int row = i >> 3, c4 = (i & 7) * 4;
            cp16(adst + (uint32_t)(row * A_STR + c4) * 4u,
                 Wp + (size_t)(o0 + row) * C_ + k0 + c4);
            cp16(bdst + (uint32_t)(row * A_STR + c4) * 4u,
                 Bp + (size_t)(n0 + row) * C_ + k0 + c4);
        }
    };

    issue(0, 0);
    CP_COMMIT();

    for (int kc = 0; kc < 12; kc++) {
        const int buf = kc & 1;
        if (kc + 1 < 12) {
            issue(kc + 1, buf ^ 1);
            CP_COMMIT();
            CP_WAIT(1);
        } else {
            CP_WAIT(0);
        }
        __syncthreads();

        const float* As_ = As + buf * P_CH;
        const float* Bs_ = Bs + buf * P_CH;

#pragma unroll
        for (int ks = 0; ks < 4; ks++) {
            const int k0 = ks * 8;
            uint32_t af[4][4], bf[4][2];
#pragma unroll
            for (int mt = 0; mt < 4; mt++) {
                const float* ap = As_ + (wm * 64 + mt * 16 + g) * A_STR + k0 + tg;
                af[mt][0] = f2tf32(ap[0]);
                af[mt][1] = f2tf32(ap[8 * A_STR]);
                af[mt][2] = f2tf32(ap[4]);
                af[mt][3] = f2tf32(ap[8 * A_STR + 4]);
            }
#pragma unroll
            for (int nt = 0; nt < 4; nt++) {
                const float* bp = Bs_ + (wn * 32 + nt * 8 + g) * A_STR + k0 + tg;
                bf[nt][0] = f2tf32(bp[0]);
                bf[nt][1] = f2tf32(bp[4]);
            }
#pragma unroll
            for (int mt = 0; mt < 4; mt++)
#pragma unroll
                for (int nt = 0; nt < 4; nt++)
                    mma_tf32(acc[mt][nt], af[mt][0], af[mt][1], af[mt][2], af[mt][3],
                             bf[nt][0], bf[nt][1]);
        }
        __syncthreads();
    }

    float* D = g_P + (size_t)b * C_ * N_;
#pragma unroll
    for (int mt = 0; mt < 4; mt++) {
        const int o = o0 + wm * 64 + mt * 16 + g;
#pragma unroll
        for (int nt = 0; nt < 4; nt++) {
            const int n = n0 + wn * 32 + nt * 8 + tg * 2;
            *(float2*)(D + (size_t)o * N_ + n)       = make_float2(acc[mt][nt][0], acc[mt][nt][1]);
            *(float2*)(D + (size_t)(o + 8) * N_ + n) = make_float2(acc[mt][nt][2], acc[mt][nt][3]);
        }
    }
}

// ---------------- K3: attention (tf32 mma.sync, 512 thr, fused PE conv) ----------------
// One CTA per (h, be). 512 threads (16 warps). 4 passes of 64 Q-rows.
// smem floats:
//   Ks [64 d][264 m]  @ 0      (16896)  raw fp32 via cp.async
//   Vs [64 d][260 m]  @ 16896  (16640)  v + pe, computed in-kernel
//   Qs [64 n][72 d]   @ 33536  (4608)   tf32-rounded, d pair-permuted
//   Sc [64 n][264 m]  @ 38144  (16896)  scores fp32 -> P tf32 (m pair-permuted)
//   Ws [64][9]        @ 55040  (576)    depthwise weights
#define KS_STR 264
#define VS_STR 260
#define QS_STR 72
#define SS_STR 264
#define OFF_KS 0
#define OFF_VS 16896
#define OFF_QS 33536
#define OFF_SC 38144
#define OFF_WS 55040
#define ATTN_FLOATS 55616   // 222464 bytes

__global__ __launch_bounds__(512, 1) void attn_mma(const float* __restrict__ Wpe)
{
    extern __shared__ float sm[];
    float* Ks  = sm + OFF_KS;
    float* Vs  = sm + OFF_VS;
    float* Qs  = sm + OFF_QS;
    float* Sc  = sm + OFF_SC;
    float* wsh = sm + OFF_WS;
    const uint32_t ks_b = smem_u32(Ks);

    const int h  = blockIdx.x;      // 0..5
    const int be = blockIdx.y;      // 0..127
    const int b  = be >> 2;
    const int sP = be & 3;

    const int t = threadIdx.x;
    const int wid = t >> 5, lane = t & 31;
    const int g = lane >> 2, tg = lane & 3;
    const int wm = wid & 3;          // 4 row-tiles of 16
    const int wq = wid >> 2;         // 0..3: QK col quarter / AV d quarter

    const float* Qg   = g_Q + ((size_t)b * C_ + h * HD) * N_ + sP * NE;
    const float* Kg   = g_K + ((size_t)b * C_ + h * HD) * N_ + sP * NE;
    const float* Vraw = g_V + ((size_t)b * C_ + h * HD) * N_;   // global n

    // ---- depthwise weights ----
    for (int i = t; i < HD * 9; i += 512)
        wsh[i] = Wpe[(h * HD) * 9 + i];

    // ---- cp.async load K (natural [d][m], coalesced) ----
#pragma unroll
    for (int j = 0; j < 8; j++) {
        int u = t + j * 512;                 // 4096 float4 units
        int d = u >> 6, m4 = (u & 63) * 4;
        cp16(ks_b + (uint32_t)(d * KS_STR + m4) * 4u, Kg + (size_t)d * N_ + m4);
    }
    CP_COMMIT();
    __syncthreads();   // wsh visible

    // ---- fused depthwise 3x3 + add: Vs[d][m] = v + pe ----
#pragma unroll
    for (int j = 0; j < 8; j++) {
        int u = t + j * 512;                 // 4096 4-wide units
        int d = u >> 6, m4 = (u & 63) * 4;
        int ng = sP * NE + m4;
        int r = ng >> 5, w0 = ng & 31;
        const float* Vrow = Vraw + (size_t)d * N_;
        const float* wp = &wsh[d * 9];
        float tap[3][6];
#pragma unroll
        for (int dr = 0; dr < 3; dr++) {
            int rr = r + dr - 1;
            bool rok = (rr >= 0 && rr < Hh);
#pragma unroll
            for (int dc = 0; dc < 6; dc++) {
                int cc = w0 + dc - 1;
                tap[dr][dc] = (rok && cc >= 0 && cc < Ww) ? Vrow[rr * Ww + cc] : 0.f;
            }
        }
#pragma unroll
        for (int e = 0; e < 4; e++) {
            float s = wp[0] * tap[0][e] + wp[1] * tap[0][e + 1] + wp[2] * tap[0][e + 2]
                    + wp[3] * tap[1][e] + wp[4] * tap[1][e + 1] + wp[5] * tap[1][e + 2]
                    + wp[6] * tap[2][e] + wp[7] * tap[2][e + 1] + wp[8] * tap[2][e + 2];
            Vs[d * VS_STR + m4 + e] = tap[1][e + 1] + s;
        }
    }

    const int c0p = perm8(2 * tg), c1p = perm8(2 * tg + 1);
    float* AOb = g_AO + (size_t)b * N_ * C_;

    for (int pass = 0; pass < 4; pass++) {
        const int n0 = pass * 64;

        // ---- Q transform: [d][n] -> Qs[n][pcol(d)], tf32-rounded ----
#pragma unroll
        for (int j = 0; j < 2; j++) {
            int u = t + j * 512;             // 1024 units: 64 d x 16 n4
            int d = u >> 4, n4 = (u & 15) * 4;
            float4 v = *(const float4*)(Qg + (size_t)d * N_ + n0 + n4);
            int pd = pcol(d);
            Qs[(n4 + 0) * QS_STR + pd] = tf32f(v.x);
            Qs[(n4 + 1) * QS_STR + pd] = tf32f(v.y);
            Qs[(n4 + 2) * QS_STR + pd] = tf32f(v.z);
            Qs[(n4 + 3) * QS_STR + pd] = tf32f(v.w);
        }
        if (pass == 0) { CP_WAIT(0); }
        __syncthreads();   // Qs/Vs ready; prior-pass Sc reads done

        // ---- QK^T: each warp 16 rows x 64 cols ----
        float acc[8][4];
#pragma unroll
        for (int i = 0; i < 8; i++) {
            acc[i][0] = 0.f; acc[i][1] = 0.f; acc[i][2] = 0.f; acc[i][3] = 0.f;
        }
#pragma unroll
        for (int ks = 0; ks < 8; ks++) {
            const float* ap = Qs + (wm * 16 + g) * QS_STR + ks * 8 + 2 * tg;
            float2 aL = *(const float2*)ap;
            float2 aH = *(const float2*)(ap + 8 * QS_STR);
            uint32_t a0 = __float_as_uint(aL.x), a2 = __float_as_uint(aL.y);
            uint32_t a1 = __float_as_uint(aH.x), a3 = __float_as_uint(aH.y);
#pragma unroll
            for (int nf = 0; nf < 8; nf++) {
                const float* bp = Ks + (ks * 8 + tg) * KS_STR + wq * 64 + nf * 8 + g;
                uint32_t b0 = f2tf32(bp[0]);
                uint32_t b1 = f2tf32(bp[4 * KS_STR]);
                mma_tf32(acc[nf], a0, a1, a2, a3, b0, b1);
            }
        }
        {
            const int r0 = wm * 16 + g;
#pragma unroll
            for (int nf = 0; nf < 8; nf++) {
                const int mb = wq * 64 + nf * 8;
                Sc[r0 * SS_STR + mb + c0p]       = acc[nf][0];
                Sc[r0 * SS_STR + mb + c1p]       = acc[nf][1];
                Sc[(r0 + 8) * SS_STR + mb + c0p] = acc[nf][2];
                Sc[(r0 + 8) * SS_STR + mb + c1p] = acc[nf][3];
            }
        }
        __syncthreads();

        // ---- softmax (warp per 4 rows); write P as tf32 in-place ----
        {
            const float scale = 0.125f;
#pragma unroll
            for (int rr = 0; rr < 4; rr++) {
                int r = wid * 4 + rr;
                float* row = &Sc[r * SS_STR];
                float vals[8];
                float mx = -1e30f;
#pragma unroll
                for (int j = 0; j < 8; j++) {
                    vals[j] = row[lane + 32 * j] * scale;
                    mx = fmaxf(mx, vals[j]);
                }
#pragma unroll
                for (int o = 16; o > 0; o >>= 1)
                    mx = fmaxf(mx, __shfl_xor_sync(0xffffffffu, mx, o));
                float sum = 0.f;
#pragma unroll
                for (int j = 0; j < 8; j++) {
                    vals[j] = __expf(vals[j] - mx);
                    sum += vals[j];
                }
#pragma unroll
                for (int o = 16; o > 0; o >>= 1)
                    sum += __shfl_xor_sync(0xffffffffu, sum, o);
                float inv = 1.f / sum;
#pragma unroll
                for (int j = 0; j < 8; j++)
                    row[lane + 32 * j] = tf32f(vals[j] * inv);
            }
        }
        __syncthreads();

        // ---- AV: each warp 16 rows x 16 d ----
        float av[2][4];
        av[0][0] = av[0][1] = av[0][2] = av[0][3] = 0.f;
        av[1][0] = av[1][1] = av[1][2] = av[1][3] = 0.f;
#pragma unroll
        for (int ks = 0; ks < 32; ks++) {
            const float* ap = Sc + (wm * 16 + g) * SS_STR + ks * 8 + 2 * tg;
            float2 aL = *(const float2*)ap;
            float2 aH = *(const float2*)(ap + 8 * SS_STR);
            uint32_t a0 = __float_as_uint(aL.x), a2 = __float_as_uint(aL.y);
            uint32_t a1 = __float_as_uint(aH.x), a3 = __float_as_uint(aH.y);
#pragma unroll
            for (int nf = 0; nf < 2; nf++) {
                const float* bp = Vs + (wq * 16 + nf * 8 + g) * VS_STR + ks * 8 + tg;
                uint32_t b0 = f2tf32(bp[0]);
                uint32_t b1 = f2tf32(bp[4]);
                mma_tf32(av[nf], a0, a1, a2, a3, b0, b1);
            }
        }

        // ---- store to AO[b][nf2][cz] ----
#pragma unroll
        for (int nf = 0; nf < 2; nf++) {
#pragma unroll
            for (int e = 0; e < 4; e++) {
                int n = n0 + wm * 16 + g + ((e >> 1) ? 8 : 0);
                int d = wq * 16 + nf * 8 + 2 * tg + (e & 1);
                unsigned lin = (unsigned)(h * HD + d) * NE + (unsigned)n;
                unsigned ne2 = lin / C_;
                unsigned cz  = lin - ne2 * C_;
                unsigned nf2 = ne2 * S_ + (unsigned)sP;
                AOb[(size_t)nf2 * C_ + cz] = av[nf][e];
            }
        }
    }
}

// ---------------- K5: BN stats (deterministic, float4) ----------------
__global__ __launch_bounds__(256) void bn_stats()
{
    const int o = blockIdx.x;
    const int t = threadIdx.x;
    float s = 0.f, sq = 0.f;
#pragma unroll 4
    for (int k = 0; k < 32; k++) {
        int u = t + k * 256;
        int b = u >> 8, n4 = (u & 255) * 4;
        float4 v = *(const float4*)(g_P + ((size_t)b * C_ + o) * N_ + n4);
        s  += v.x + v.y + v.z + v.w;
        sq += v.x * v.x + v.y * v.y + v.z * v.z + v.w * v.w;
    }
    __shared__ float rs[256], rq[256];
    rs[t] = s; rq[t] = sq;
    __syncthreads();
    for (int st = 128; st > 0; st >>= 1) {
        if (t < st) { rs[t] += rs[t + st]; rq[t] += rq[t + st]; }
        __syncthreads();
    }
    if (t == 0) {
        float inv_n = 1.f / (float)(B_ * N_);
        float mu  = rs[0] * inv_n;
        float var = rq[0] * inv_n - mu * mu;
        g_mean[o] = mu;
        g_rstd[o] = rsqrtf(var + EPS_);
    }
}

// ---------------- K6: residual + BN normalize (float4) ----------------
__global__ __launch_bounds__(256) void final_kernel(
    const float* __restrict__ x,
    const float* __restrict__ gamma,
    const float* __restrict__ beta,
    float* __restrict__ out)
{
    int idx = (blockIdx.x * 256 + threadIdx.x) * 4;
    int c = (idx / N_) % C_;
    float ga = gamma[c], be = beta[c], mu = g_mean[c], rs = g_rstd[c];
    float4 v = *(const float4*)(g_P + idx);
    float4 xv = *(const float4*)(x + idx);
    float4 r;
    r.x = xv.x + ga * (v.x - mu) * rs + be;
    r.y = xv.y + ga * (v.y - mu) * rs + be;
    r.z = xv.z + ga * (v.z - mu) * rs + be;
    r.w = xv.w + ga * (v.w - mu) * rs + be;
    *(float4*)(out + idx) = r;
}

// ---------------- launch ----------------
extern "C" void kernel_launch(void* const* d_in, const int* in_sizes, int n_in,
                              void* d_out, int out_size)
{
    const float* x     = (const float*)d_in[0];
    const float* Wq    = (const float*)d_in[1];
    const float* Wk    = (const float*)d_in[2];
    const float* Wv    = (const float*)d_in[3];
    const float* Wpe   = (const float*)d_in[4];
    const float* Wproj = (const float*)d_in[5];
    const float* gamma = (const float*)d_in[6];
    const float* beta  = (const float*)d_in[7];
    float* out = (float*)d_out;

    static bool attr_set = false;
    if (!attr_set) {
        cudaFuncSetAttribute(qkv_mma, cudaFuncAttributeMaxDynamicSharedMemorySize,
                             GS_FLOATS * (int)sizeof(float));
        cudaFuncSetAttribute(proj_mma, cudaFuncAttributeMaxDynamicSharedMemorySize,
                             PS_FLOATS * (int)sizeof(float));
        cudaFuncSetAttribute(attn_mma, cudaFuncAttributeMaxDynamicSharedMemorySize,
                             ATTN_FLOATS * (int)sizeof(float));
        attr_set = true;
    }

    qkv_mma<<<dim3(N_ / 128, 9, B_), 256, GS_FLOATS * sizeof(float)>>>(Wq, Wk, Wv, x);

    attn_mma<<<dim3(NHEAD, 128), 512, ATTN_FLOATS * sizeof(float)>>>(Wpe);

    proj_mma<<<dim3(N_ / 128, C_ / 128, B_), 256, PS_FLOATS * sizeof(float)>>>(Wproj);

    bn_stats<<<C_, 256>>>();

    final_kernel<<<(B_ * C_ * N_) / 1024, 256>>>(x, gamma, beta, out);
}